// round 11
// baseline (speedup 1.0000x reference)
#include <cuda_runtime.h>
#include <cuda_fp16.h>
#include <cstdint>
#include <math.h>

// Problem constants
#define Bv   2
#define Sv   2048
#define Dv   4096
#define Hv   32
#define KVHv 8
#define HDv  128
#define Mv   (Bv * Sv)       // 4096
#define NQ   (Hv * HDv)      // 4096
#define NKV  (KVHv * HDv)    // 1024
#define NQKV (NQ + 2 * NKV)  // 6144

// fp16 split-precision scratch
__device__ __half g_x_hi[(size_t)Mv * Dv],   g_x_lo[(size_t)Mv * Dv];
__device__ __half g_wqkv_hi[(size_t)NQKV * Dv];
__device__ __half g_wo_hi[(size_t)Dv * NQ];
__device__ __half g_at_hi[(size_t)Mv * NQ],  g_at_lo[(size_t)Mv * NQ];
__device__ __half g_qr_hi[(size_t)Mv * NQ],  g_qr_lo[(size_t)Mv * NQ];
__device__ __half g_kr_hi[(size_t)Mv * NKV];
__device__ __half g_vs_hi[(size_t)Mv * NKV];

// ---------------------------------------------------------------------------
// Helpers (compute_103-safe)
// ---------------------------------------------------------------------------
__device__ __forceinline__ uint32_t smem_u32(const void* p) {
    uint32_t a;
    asm("{ .reg .u64 t; cvta.to.shared.u64 t, %1; cvt.u32.u64 %0, t; }" : "=r"(a) : "l"(p));
    return a;
}
__device__ __forceinline__ void cp16(uint32_t dst, const void* src) {
    asm volatile("cp.async.cg.shared.global [%0], [%1], 16;" :: "r"(dst), "l"(src));
}
#define CP_COMMIT() asm volatile("cp.async.commit_group;" ::: "memory")
#define CP_WAIT1()  asm volatile("cp.async.wait_group 1;" ::: "memory")
#define CP_WAIT0()  asm volatile("cp.async.wait_group 0;" ::: "memory")

__device__ __forceinline__ void mma_f16(float* c, const uint32_t* a, const uint32_t* b) {
    asm volatile("mma.sync.aligned.m16n8k16.row.col.f32.f16.f16.f32 "
        "{%0,%1,%2,%3}, {%4,%5,%6,%7}, {%8,%9}, {%0,%1,%2,%3};"
        : "+f"(c[0]), "+f"(c[1]), "+f"(c[2]), "+f"(c[3])
        : "r"(a[0]), "r"(a[1]), "r"(a[2]), "r"(a[3]), "r"(b[0]), "r"(b[1]));
}
__device__ __forceinline__ void ldsm_x4(uint32_t* r, uint32_t addr) {
    asm volatile("ldmatrix.sync.aligned.m8n8.x4.shared.b16 {%0,%1,%2,%3}, [%4];"
        : "=r"(r[0]), "=r"(r[1]), "=r"(r[2]), "=r"(r[3]) : "r"(addr));
}
__device__ __forceinline__ void ldsm_x4_t(uint32_t* r, uint32_t addr) {
    asm volatile("ldmatrix.sync.aligned.m8n8.x4.trans.shared.b16 {%0,%1,%2,%3}, [%4];"
        : "=r"(r[0]), "=r"(r[1]), "=r"(r[2]), "=r"(r[3]) : "r"(addr));
}
__device__ __forceinline__ uint32_t pack2h(float x, float y) {
    __half2 t = __floats2half2_rn(x, y);
    return *(uint32_t*)&t;
}

// ---------------------------------------------------------------------------
// Split fp32 -> fp16 hi/lo ; and hi-only variant
// ---------------------------------------------------------------------------
__global__ void cvt_split(const float* __restrict__ in,
                          __half* __restrict__ hi,
                          __half* __restrict__ lo, long n4) {
    long i = (long)blockIdx.x * blockDim.x + threadIdx.x;
    if (i >= n4) return;
    float4 v = ((const float4*)in)[i];
    float vv[4] = {v.x, v.y, v.z, v.w};
    __half h[4], l[4];
#pragma unroll
    for (int j = 0; j < 4; j++) {
        h[j] = __float2half_rn(vv[j]);
        l[j] = __float2half_rn(vv[j] - __half2float(h[j]));
    }
    ((__half2*)hi)[i * 2]     = __half2(h[0], h[1]);
    ((__half2*)hi)[i * 2 + 1] = __half2(h[2], h[3]);
    ((__half2*)lo)[i * 2]     = __half2(l[0], l[1]);
    ((__half2*)lo)[i * 2 + 1] = __half2(l[2], l[3]);
}

__global__ void cvt_hi(const float* __restrict__ in,
                       __half* __restrict__ hi, long n4) {
    long i = (long)blockIdx.x * blockDim.x + threadIdx.x;
    if (i >= n4) return;
    float4 v = ((const float4*)in)[i];
    ((__half2*)hi)[i * 2]     = __floats2half2_rn(v.x, v.y);
    ((__half2*)hi)[i * 2 + 1] = __floats2half2_rn(v.z, v.w);
}

// ---------------------------------------------------------------------------
// HMMA fp16x2 GEMM: C = (Ahi+Alo) @ Bhi^T.
// 128x256 CTA tile, 512 threads (16 warps, warp tile 32x64), BK=32,
// 3-stage pipeline (32KB/stage = Ahi+Alo+Bhi), 96KB smem, 1 CTA/SM,
// persistent grid of 148. Swizzled 64B rows, ldmatrix loads.
// EPI=1: fused RoPE + split epilogue (Q: hi+lo; K,V: hi); EPI=0: fp32 C.
// ---------------------------------------------------------------------------
#define BM 128
#define BN 256
#define BK 32
#define TILE_A    (128 * 64)              // 8192 B
#define TILE_B    (256 * 64)              // 16384 B
#define STAGE_SM  (2 * TILE_A + TILE_B)   // 32768 B
#define GEMM_SMEM (3 * STAGE_SM)          // 98304 B
#define SWZ(r, c16) ((c16) ^ (((r) >> 1) & 3))
#define GEMM_GRID 148

__device__ __forceinline__ void load_stage(
    uint32_t sbase,
    const __half* __restrict__ Ahi, const __half* __restrict__ Alo,
    const __half* __restrict__ Bhi,
    int m0, int n0, int k0, int K, int tid)
{
#pragma unroll
    for (int j = 0; j < 4; j++) {
        if (j < 2) {
            // A hi/lo: 512 chunks each
            const int row = tid >> 2;
            const int c16 = tid & 3;
            const uint32_t soff = sbase + j * TILE_A + row * 64 + (SWZ(row, c16) << 4);
            const __half* g = (j == 0) ? Ahi : Alo;
            cp16(soff, g + (size_t)(m0 + row) * K + k0 + c16 * 8);
        } else {
            // B: 1024 chunks
            const int cc = tid + (j - 2) * 512;
            const int row = cc >> 2;
            const int c16 = cc & 3;
            const uint32_t soff = sbase + 2 * TILE_A + row * 64 + (SWZ(row, c16) << 4);
            cp16(soff, Bhi + (size_t)(n0 + row) * K + k0 + c16 * 8);
        }
    }
}

template <bool EPI>
__global__ __launch_bounds__(512, 1) void gemm_hmma_x2(
    const __half* __restrict__ Ahi, const __half* __restrict__ Alo,
    const __half* __restrict__ Bhi,
    float* __restrict__ C,
    __half* __restrict__ Qh, __half* __restrict__ Ql,
    __half* __restrict__ Kh, __half* __restrict__ Vh,
    const float* __restrict__ cs, const float* __restrict__ sn,
    int N, int K)
{
    extern __shared__ char smem[];
    const uint32_t sb = smem_u32(smem);
    const int tid = threadIdx.x;
    const int wid = tid >> 5, lane = tid & 31;
    const int wm = wid & 3;        // 4 warps in M, 32 rows each
    const int wn = wid >> 2;       // 4 warps in N, 64 cols each
    const int lr = lane >> 2;

    const int nt_n = N / BN;
    const int ntiles = (Mv / BM) * nt_n;
    const int NIT = K / BK;

    const int a_row = lane & 15;
    const int a_chi = lane >> 4;
    const int b_row = (lane & 7) + ((lane >> 4) << 3);
    const int b_chi = (lane >> 3) & 1;

    for (int t = blockIdx.x; t < ntiles; t += GEMM_GRID) {
        const int m0 = (t / nt_n) * BM;
        const int n0 = (t % nt_n) * BN;

        float acc[2][8][4];
#pragma unroll
        for (int mt = 0; mt < 2; mt++)
#pragma unroll
            for (int nf = 0; nf < 8; nf++)
#pragma unroll
                for (int r = 0; r < 4; r++) acc[mt][nf][r] = 0.f;

        __syncthreads();   // all warps done with previous tile's smem

        load_stage(sb,            Ahi, Alo, Bhi, m0, n0, 0,  K, tid);
        CP_COMMIT();
        load_stage(sb + STAGE_SM, Ahi, Alo, Bhi, m0, n0, BK, K, tid);
        CP_COMMIT();

        for (int it = 0; it < NIT; ++it) {
            CP_WAIT1();
            __syncthreads();
            if (it + 2 < NIT)
                load_stage(sb + ((it + 2) % 3) * STAGE_SM,
                           Ahi, Alo, Bhi, m0, n0, (it + 2) * BK, K, tid);
            CP_COMMIT();   // always commit to keep group counting fixed

            const uint32_t sA = sb + (it % 3) * STAGE_SM;
            const uint32_t sB = sA + 2 * TILE_A;
#pragma unroll
            for (int kk = 0; kk < 2; kk++) {
                uint32_t ah[2][4], al[2][4], bh[4][4];
#pragma unroll
                for (int mt = 0; mt < 2; mt++) {
                    const int r = wm * 32 + mt * 16 + a_row;
                    const int c = kk * 2 + a_chi;
                    const uint32_t aaddr = sA + r * 64 + (SWZ(r, c) << 4);
                    ldsm_x4(ah[mt], aaddr);
                    ldsm_x4(al[mt], aaddr + TILE_A);
                }
#pragma unroll
                for (int g = 0; g < 4; g++) {
                    const int r = wn * 64 + g * 16 + b_row;
                    const int c = kk * 2 + b_chi;
                    ldsm_x4(bh[g], sB + r * 64 + (SWZ(r, c) << 4));
                }
#pragma unroll
                for (int mt = 0; mt < 2; mt++)
#pragma unroll
                    for (int nf = 0; nf < 8; nf++) {
                        const uint32_t* bhf = bh[nf >> 1] + (nf & 1) * 2;
                        mma_f16(acc[mt][nf], ah[mt], bhf);
                        mma_f16(acc[mt][nf], al[mt], bhf);
                    }
            }
        }

        if (!EPI) {
#pragma unroll
            for (int mt = 0; mt < 2; mt++) {
                const int row = m0 + wm * 32 + mt * 16 + lr;
#pragma unroll
                for (int nf = 0; nf < 8; nf++) {
                    const int col = n0 + wn * 64 + nf * 8 + (lane & 3) * 2;
                    float2* p0 = (float2*)&C[(size_t)row * N + col];
                    float2* p1 = (float2*)&C[(size_t)(row + 8) * N + col];
                    *p0 = make_float2(acc[mt][nf][0], acc[mt][nf][1]);
                    *p1 = make_float2(acc[mt][nf][2], acc[mt][nf][3]);
                }
            }
        } else {
            // regions (BN=256 divides all): [0,NQ): Q hi+lo + rope;
            // [NQ,NQ+NKV): K hi + rope; rest: V hi
            __half *Dh, *Dl = nullptr;
            int dstride, coff;
            bool dorope;
            if (n0 < NQ)            { Dh = Qh; Dl = Ql; dstride = NQ;  coff = 0;        dorope = true; }
            else if (n0 < NQ + NKV) { Dh = Kh;          dstride = NKV; coff = NQ;       dorope = true; }
            else                    { Dh = Vh;          dstride = NKV; coff = NQ + NKV; dorope = false; }
            const bool wlo = (n0 < NQ);
#pragma unroll
            for (int mt = 0; mt < 2; mt++) {
#pragma unroll
                for (int nf = 0; nf < 8; nf++) {
                    const int col = n0 + wn * 64 + nf * 8 + (lane & 3) * 2;
                    const int fi = (col & 127) >> 1;
#pragma unroll
                    for (int r = 0; r < 2; r++) {
                        const int row = m0 + wm * 32 + mt * 16 + lr + 8 * r;
                        float x0 = acc[mt][nf][2 * r];
                        float x1 = acc[mt][nf][2 * r + 1];
                        float y0 = x0, y1 = x1;
                        if (dorope) {
                            const int s = row & (Sv - 1);
                            const float c  = __ldg(cs + s * 64 + fi);
                            const float sv = __ldg(sn + s * 64 + fi);
                            y0 = x0 * c - x1 * sv;
                            y1 = x0 * sv + x1 * c;
                        }
                        const uint32_t hw = pack2h(y0, y1);
                        const size_t o = (size_t)row * dstride + (col - coff);
                        *(uint32_t*)&Dh[o] = hw;
                        if (wlo) {
                            __half2 hb = *(__half2*)&hw;
                            *(uint32_t*)&Dl[o] =
                                pack2h(y0 - __half2float(hb.x), y1 - __half2float(hb.y));
                        }
                    }
                }
            }
        }
    }
}

// ---------------------------------------------------------------------------
// HMMA flash attention, fp16 2-pass (unchanged from R10).
// CTA = 64 q-rows, 128 threads, K/V hi tiles of 32 rows double-buffered,
// Q hi+lo register-resident. ~70KB smem, 2 CTAs/SM, longest-first order.
// ---------------------------------------------------------------------------
#define FROWB 272
#define FQ_HALF  (64 * FROWB)
#define FK_HALF  (32 * FROWB)
#define SM_KV    (2 * FQ_HALF)
#define KV_STAGE (2 * FK_HALF)
#define FLASH_SMEM (SM_KV + 2 * KV_STAGE)   // 69632

__device__ __forceinline__ void flash_load_kv(
    uint32_t sb, int stage,
    const __half* __restrict__ Kh, const __half* __restrict__ Vh,
    size_t gbase, int tid)
{
#pragma unroll
    for (int j = 0; j < 8; j++) {
        const int t = j >> 2;
        const int cc = tid + (j & 3) * 128;
        const int row = cc >> 4, c16 = cc & 15;
        const __half* g = (t == 0) ? Kh : Vh;
        const uint32_t soff = sb + SM_KV + stage * KV_STAGE + t * FK_HALF
                              + row * FROWB + c16 * 16;
        cp16(soff, g + gbase + (size_t)row * NKV + c16 * 8);
    }
}

__global__ __launch_bounds__(128, 2) void flash_hmma(
    const __half* __restrict__ Qh_g, const __half* __restrict__ Ql_g,
    const __half* __restrict__ Kh_g, const __half* __restrict__ Vh_g,
    __half* __restrict__ Oh, __half* __restrict__ Ol)
{
    extern __shared__ char smem[];
    const uint32_t sb = smem_u32(smem);
    const int tid = threadIdx.x, w = tid >> 5, lane = tid & 31;
    const int lr = lane >> 2, lc = lane & 3;
    const int qb = gridDim.x - 1 - blockIdx.x;   // longest-first
    const int q0 = qb * 64, h = blockIdx.y, b = blockIdx.z;
    const int kvh = h >> 2;
    const float scale = 0.08838834764831845f;

    {
        const size_t gq = ((size_t)(b * Sv + q0)) * NQ + h * HDv;
#pragma unroll
        for (int j = 0; j < 16; j++) {
            const int hl = j >> 3;
            const int cc = tid + (j & 7) * 128;
            const int row = cc >> 4, c16 = cc & 15;
            const __half* g = hl ? Ql_g : Qh_g;
            cp16(sb + hl * FQ_HALF + row * FROWB + c16 * 16,
                 g + gq + (size_t)row * NQ + c16 * 8);
        }
    }
    CP_COMMIT();
    flash_load_kv(sb, 0, Kh_g, Vh_g, ((size_t)(b * Sv)) * NKV + kvh * HDv, tid);
    CP_COMMIT();

    const int a_row = lane & 15;
    const int a_cb  = (lane >> 4) << 4;
    const int b_row = (lane & 7) + ((lane >> 4) << 3);
    const int b_cb  = ((lane >> 3) & 1) << 4;

    CP_WAIT1();
    __syncthreads();
    uint32_t qh[8][4], ql[8][4];
#pragma unroll
    for (int kf = 0; kf < 8; kf++) {
        const uint32_t qaddr = sb + (w * 16 + a_row) * FROWB + kf * 32 + a_cb;
        ldsm_x4(qh[kf], qaddr);
        ldsm_x4(ql[kf], qaddr + FQ_HALF);
    }

    float o[16][4];
#pragma unroll
    for (int i = 0; i < 16; i++)
#pragma unroll
        for (int j = 0; j < 4; j++) o[i][j] = 0.f;
    float mrow[2] = {-1e30f, -1e30f};
    float lrow[2] = {0.f, 0.f};

    const int ktmax = 2 * qb + 1;
    for (int kt = 0; kt <= ktmax; ++kt) {
        CP_WAIT0();
        __syncthreads();
        if (kt < ktmax) {
            flash_load_kv(sb, (kt + 1) & 1, Kh_g, Vh_g,
                          ((size_t)(b * Sv + (kt + 1) * 32)) * NKV + kvh * HDv, tid);
            CP_COMMIT();
        }

        const int k0 = kt * 32;
        if (k0 > q0 + w * 16 + 15) continue;

        const uint32_t Kst = sb + SM_KV + (kt & 1) * KV_STAGE;
        const uint32_t Vst = Kst + FK_HALF;

        float s[4][4];
#pragma unroll
        for (int nf = 0; nf < 4; nf++)
#pragma unroll
            for (int r = 0; r < 4; r++) s[nf][r] = 0.f;

#pragma unroll
        for (int kf = 0; kf < 8; kf++) {
#pragma unroll
            for (int nfp = 0; nfp < 2; nfp++) {
                const uint32_t kaddr = Kst + (nfp * 16 + b_row) * FROWB + kf * 32 + b_cb;
                uint32_t bh4[4];
                ldsm_x4(bh4, kaddr);
                mma_f16(s[2 * nfp],     qh[kf], bh4);
                mma_f16(s[2 * nfp],     ql[kf], bh4);
                mma_f16(s[2 * nfp + 1], qh[kf], bh4 + 2);
                mma_f16(s[2 * nfp + 1], ql[kf], bh4 + 2);
            }
        }

        const bool diag = (k0 + 31 > q0 + w * 16);
#pragma unroll
        for (int r = 0; r < 2; r++) {
            const int qrow = q0 + w * 16 + lr + 8 * r;
            float mx = -1e30f;
#pragma unroll
            for (int nf = 0; nf < 4; nf++) {
                float v0 = s[nf][2 * r] * scale;
                float v1 = s[nf][2 * r + 1] * scale;
                if (diag) {
                    const int col = k0 + nf * 8 + lc * 2;
                    if (col > qrow) v0 = -1e30f;
                    if (col + 1 > qrow) v1 = -1e30f;
                }
                s[nf][2 * r] = v0;
                s[nf][2 * r + 1] = v1;
                mx = fmaxf(mx, fmaxf(v0, v1));
            }
            mx = fmaxf(mx, __shfl_xor_sync(0xffffffffu, mx, 1));
            mx = fmaxf(mx, __shfl_xor_sync(0xffffffffu, mx, 2));
            const float m_new = fmaxf(mrow[r], mx);
            const float alpha = __expf(mrow[r] - m_new);
            mrow[r] = m_new;
            float sum = 0.f;
#pragma unroll
            for (int nf = 0; nf < 4; nf++) {
                float p0 = __expf(s[nf][2 * r] - m_new);
                float p1 = __expf(s[nf][2 * r + 1] - m_new);
                s[nf][2 * r] = p0;
                s[nf][2 * r + 1] = p1;
                sum += p0 + p1;
            }
            sum += __shfl_xor_sync(0xffffffffu, sum, 1);
            sum += __shfl_xor_sync(0xffffffffu, sum, 2);
            lrow[r] = lrow[r] * alpha + sum;
#pragma unroll
            for (int nf2 = 0; nf2 < 16; nf2++) {
                o[nf2][2 * r] *= alpha;
                o[nf2][2 * r + 1] *= alpha;
            }
        }

        uint32_t phi[2][4], plo[2][4];
#pragma unroll
        for (int kf2 = 0; kf2 < 2; kf2++) {
#pragma unroll
            for (int m = 0; m < 2; m++) {
                const int nf = 2 * kf2 + m;
                float x0 = s[nf][0], x1 = s[nf][1], x2 = s[nf][2], x3 = s[nf][3];
                uint32_t h01 = pack2h(x0, x1), h23 = pack2h(x2, x3);
                phi[kf2][2 * m]     = h01;
                phi[kf2][2 * m + 1] = h23;
                __half2 b01 = *(__half2*)&h01;
                __half2 b23 = *(__half2*)&h23;
                plo[kf2][2 * m]     = pack2h(x0 - __half2float(b01.x),
                                             x1 - __half2float(b01.y));
                plo[kf2][2 * m + 1] = pack2h(x2 - __half2float(b23.x),
                                             x3 - __half2float(b23.y));
            }
        }

#pragma unroll
        for (int kf2 = 0; kf2 < 2; kf2++) {
#pragma unroll
            for (int nfp = 0; nfp < 8; nfp++) {
                const uint32_t va = Vst + (kf2 * 16 + (lane & 15)) * FROWB
                                    + (nfp * 16 + ((lane >> 4) << 3)) * 2;
                uint32_t bh4[4];
                ldsm_x4_t(bh4, va);
                mma_f16(o[2 * nfp],     phi[kf2], bh4);
                mma_f16(o[2 * nfp],     plo[kf2], bh4);
                mma_f16(o[2 * nfp + 1], phi[kf2], bh4 + 2);
                mma_f16(o[2 * nfp + 1], plo[kf2], bh4 + 2);
            }
        }
    }

#pragma unroll
    for (int r = 0; r < 2; r++) {
        const float inv = 1.f / lrow[r];
        const int row = q0 + w * 16 + lr + 8 * r;
        const size_t base = ((size_t)(b * Sv + row)) * NQ + h * HDv + lc * 2;
#pragma unroll
        for (int nf2 = 0; nf2 < 16; nf2++) {
            float y0 = o[nf2][2 * r] * inv;
            float y1 = o[nf2][2 * r + 1] * inv;
            uint32_t hw = pack2h(y0, y1);
            __half2 hb = *(__half2*)&hw;
            uint32_t lw = pack2h(y0 - __half2float(hb.x),
                                 y1 - __half2float(hb.y));
            *(uint32_t*)&Oh[base + nf2 * 8] = hw;
            *(uint32_t*)&Ol[base + nf2 * 8] = lw;
        }
    }
}

// ---------------------------------------------------------------------------
// Launch. Inputs: 0=x 1=cos 2=sin 3=positions 4=mask 5=wq 6=wk 7=wv 8=wo
// ---------------------------------------------------------------------------
extern "C" void kernel_launch(void* const* d_in, const int* in_sizes, int n_in,
                              void* d_out, int out_size)
{
    const float* x  = (const float*)d_in[0];
    const float* fc = (const float*)d_in[1];
    const float* fs = (const float*)d_in[2];
    const float* wq = (const float*)d_in[5];
    const float* wk = (const float*)d_in[6];
    const float* wv = (const float*)d_in[7];
    const float* wo = (const float*)d_in[8];
    float* out = (float*)d_out;

    __half *xh, *xl, *wh, *oh, *ah, *al, *qrh, *qrl, *krh, *vsh;
    cudaGetSymbolAddress((void**)&xh, g_x_hi);    cudaGetSymbolAddress((void**)&xl, g_x_lo);
    cudaGetSymbolAddress((void**)&wh, g_wqkv_hi);
    cudaGetSymbolAddress((void**)&oh, g_wo_hi);
    cudaGetSymbolAddress((void**)&ah, g_at_hi);   cudaGetSymbolAddress((void**)&al, g_at_lo);
    cudaGetSymbolAddress((void**)&qrh, g_qr_hi);  cudaGetSymbolAddress((void**)&qrl, g_qr_lo);
    cudaGetSymbolAddress((void**)&krh, g_kr_hi);
    cudaGetSymbolAddress((void**)&vsh, g_vs_hi);

    // conversions: x -> hi+lo; weights -> hi only (concatenated wqkv)
    {
        long n4;
        n4 = (long)Mv * Dv / 4;
        cvt_split<<<(unsigned)((n4 + 255) / 256), 256>>>(x, xh, xl, n4);
        n4 = (long)NQ * Dv / 4;
        cvt_hi<<<(unsigned)((n4 + 255) / 256), 256>>>(wq, wh, n4);
        n4 = (long)NKV * Dv / 4;
        cvt_hi<<<(unsigned)((n4 + 255) / 256), 256>>>(wk, wh + (size_t)NQ * Dv, n4);
        cvt_hi<<<(unsigned)((n4 + 255) / 256), 256>>>(wv, wh + (size_t)(NQ + NKV) * Dv, n4);
        n4 = (long)Dv * NQ / 4;
        cvt_hi<<<(unsigned)((n4 + 255) / 256), 256>>>(wo, oh, n4);
    }

    cudaFuncSetAttribute(gemm_hmma_x2<true>,
                         cudaFuncAttributeMaxDynamicSharedMemorySize, GEMM_SMEM);
    cudaFuncSetAttribute(gemm_hmma_x2<false>,
                         cudaFuncAttributeMaxDynamicSharedMemorySize, GEMM_SMEM);

    // Fused QKV projection + RoPE + split (persistent, 128x256 tiles)
    gemm_hmma_x2<true><<<GEMM_GRID, 512, GEMM_SMEM>>>(
        xh, xl, wh, nullptr,
        qrh, qrl, krh, vsh, fc, fs, NQKV, Dv);

    // Flash attention (fp16 2-pass, 2 CTAs/SM, longest-first)
    cudaFuncSetAttribute(flash_hmma, cudaFuncAttributeMaxDynamicSharedMemorySize, FLASH_SMEM);
    flash_hmma<<<dim3(Sv / 64, Hv, Bv), 128, FLASH_SMEM>>>(
        qrh, qrl, krh, vsh, ah, al);

    // Output projection (persistent, 128x256 tiles)
    gemm_hmma_x2<false><<<GEMM_GRID, 512, GEMM_SMEM>>>(
        ah, al, oh, out,
        nullptr, nullptr, nullptr, nullptr, nullptr, nullptr, NQ, Dv);
}

// round 12
// speedup vs baseline: 1.2763x; 1.2763x over previous
#include <cuda_runtime.h>
#include <cuda_fp16.h>
#include <cstdint>
#include <math.h>

// Problem constants
#define Bv   2
#define Sv   2048
#define Dv   4096
#define Hv   32
#define KVHv 8
#define HDv  128
#define Mv   (Bv * Sv)       // 4096
#define NQ   (Hv * HDv)      // 4096
#define NKV  (KVHv * HDv)    // 1024
#define NQKV (NQ + 2 * NKV)  // 6144

// fp16 split-precision scratch
__device__ __half g_x_hi[(size_t)Mv * Dv],   g_x_lo[(size_t)Mv * Dv];
__device__ __half g_wqkv_hi[(size_t)NQKV * Dv];
__device__ __half g_wo_hi[(size_t)Dv * NQ];
__device__ __half g_at_hi[(size_t)Mv * NQ];
__device__ __half g_qr_hi[(size_t)Mv * NQ],  g_qr_lo[(size_t)Mv * NQ];
__device__ __half g_kr_hi[(size_t)Mv * NKV];
__device__ __half g_vs_hi[(size_t)Mv * NKV];

// ---------------------------------------------------------------------------
// Helpers (compute_103-safe)
// ---------------------------------------------------------------------------
__device__ __forceinline__ uint32_t smem_u32(const void* p) {
    uint32_t a;
    asm("{ .reg .u64 t; cvta.to.shared.u64 t, %1; cvt.u32.u64 %0, t; }" : "=r"(a) : "l"(p));
    return a;
}
__device__ __forceinline__ void cp16(uint32_t dst, const void* src) {
    asm volatile("cp.async.cg.shared.global [%0], [%1], 16;" :: "r"(dst), "l"(src));
}
#define CP_COMMIT() asm volatile("cp.async.commit_group;" ::: "memory")
#define CP_WAIT1()  asm volatile("cp.async.wait_group 1;" ::: "memory")
#define CP_WAIT0()  asm volatile("cp.async.wait_group 0;" ::: "memory")

__device__ __forceinline__ void mma_f16(float* c, const uint32_t* a, const uint32_t* b) {
    asm volatile("mma.sync.aligned.m16n8k16.row.col.f32.f16.f16.f32 "
        "{%0,%1,%2,%3}, {%4,%5,%6,%7}, {%8,%9}, {%0,%1,%2,%3};"
        : "+f"(c[0]), "+f"(c[1]), "+f"(c[2]), "+f"(c[3])
        : "r"(a[0]), "r"(a[1]), "r"(a[2]), "r"(a[3]), "r"(b[0]), "r"(b[1]));
}
__device__ __forceinline__ void ldsm_x4(uint32_t* r, uint32_t addr) {
    asm volatile("ldmatrix.sync.aligned.m8n8.x4.shared.b16 {%0,%1,%2,%3}, [%4];"
        : "=r"(r[0]), "=r"(r[1]), "=r"(r[2]), "=r"(r[3]) : "r"(addr));
}
__device__ __forceinline__ void ldsm_x4_t(uint32_t* r, uint32_t addr) {
    asm volatile("ldmatrix.sync.aligned.m8n8.x4.trans.shared.b16 {%0,%1,%2,%3}, [%4];"
        : "=r"(r[0]), "=r"(r[1]), "=r"(r[2]), "=r"(r[3]) : "r"(addr));
}
__device__ __forceinline__ uint32_t pack2h(float x, float y) {
    __half2 t = __floats2half2_rn(x, y);
    return *(uint32_t*)&t;
}

// ---------------------------------------------------------------------------
// Split fp32 -> fp16 hi/lo ; and hi-only variant
// ---------------------------------------------------------------------------
__global__ void cvt_split(const float* __restrict__ in,
                          __half* __restrict__ hi,
                          __half* __restrict__ lo, long n4) {
    long i = (long)blockIdx.x * blockDim.x + threadIdx.x;
    if (i >= n4) return;
    float4 v = ((const float4*)in)[i];
    float vv[4] = {v.x, v.y, v.z, v.w};
    __half h[4], l[4];
#pragma unroll
    for (int j = 0; j < 4; j++) {
        h[j] = __float2half_rn(vv[j]);
        l[j] = __float2half_rn(vv[j] - __half2float(h[j]));
    }
    ((__half2*)hi)[i * 2]     = __half2(h[0], h[1]);
    ((__half2*)hi)[i * 2 + 1] = __half2(h[2], h[3]);
    ((__half2*)lo)[i * 2]     = __half2(l[0], l[1]);
    ((__half2*)lo)[i * 2 + 1] = __half2(l[2], l[3]);
}

__global__ void cvt_hi(const float* __restrict__ in,
                       __half* __restrict__ hi, long n4) {
    long i = (long)blockIdx.x * blockDim.x + threadIdx.x;
    if (i >= n4) return;
    float4 v = ((const float4*)in)[i];
    ((__half2*)hi)[i * 2]     = __floats2half2_rn(v.x, v.y);
    ((__half2*)hi)[i * 2 + 1] = __floats2half2_rn(v.z, v.w);
}

// ---------------------------------------------------------------------------
// HMMA fp16x2 GEMM (R10, proven): C = (Ahi+Alo) @ Bhi^T.
// 128x128 CTA tile, BK=32, 3-stage pipeline (Ahi,Alo,Bhi = 24KB/stage),
// 72KB smem, 2 CTAs/SM, swizzled 64B rows, ldmatrix loads.
// EPI=1: fused RoPE + split epilogue (Q: hi+lo; K,V: hi); EPI=0: fp32 C.
// ---------------------------------------------------------------------------
#define BM 128
#define BN 128
#define BK 32
#define TILE_SM   (128 * 64)          // 8192 B
#define STAGE_SM  (3 * TILE_SM)       // 24576 B (Ahi, Alo, Bhi)
#define GEMM_SMEM (3 * STAGE_SM)      // 73728 B
#define SWZ(r, c16) ((c16) ^ (((r) >> 1) & 3))

__device__ __forceinline__ void load_stage(
    uint32_t sbase,
    const __half* __restrict__ Ahi, const __half* __restrict__ Alo,
    const __half* __restrict__ Bhi,
    int m0, int n0, int k0, int K, int tid)
{
#pragma unroll
    for (int j = 0; j < 6; j++) {
        const int tile = j >> 1;              // 0:Ahi 1:Alo 2:Bhi
        const int cc = tid + (j & 1) * 256;   // 0..511 within tile
        const int row = cc >> 2;
        const int c16 = cc & 3;
        const uint32_t soff = sbase + tile * TILE_SM + row * 64 + (SWZ(row, c16) << 4);
        const __half* g = (tile == 0) ? Ahi : (tile == 1) ? Alo : Bhi;
        const int grow = (tile < 2) ? (m0 + row) : (n0 + row);
        cp16(soff, g + (size_t)grow * K + k0 + c16 * 8);
    }
}

template <bool EPI>
__global__ __launch_bounds__(256, 2) void gemm_hmma_x2(
    const __half* __restrict__ Ahi, const __half* __restrict__ Alo,
    const __half* __restrict__ Bhi,
    float* __restrict__ C,
    __half* __restrict__ Qh, __half* __restrict__ Ql,
    __half* __restrict__ Kh, __half* __restrict__ Vh,
    const float* __restrict__ cs, const float* __restrict__ sn,
    int N, int K)
{
    extern __shared__ char smem[];
    const uint32_t sb = smem_u32(smem);
    const int tid = threadIdx.x;
    const int wid = tid >> 5, lane = tid & 31;
    const int wm = wid & 1;
    const int wn = wid >> 1;
    const int lr = lane >> 2;
    const int m0 = blockIdx.y * BM, n0 = blockIdx.x * BN;

    float acc[4][4][4];
#pragma unroll
    for (int mt = 0; mt < 4; mt++)
#pragma unroll
        for (int nt = 0; nt < 4; nt++)
#pragma unroll
            for (int r = 0; r < 4; r++) acc[mt][nt][r] = 0.f;

    const int NIT = K / BK;

    load_stage(sb,            Ahi, Alo, Bhi, m0, n0, 0,  K, tid);
    CP_COMMIT();
    load_stage(sb + STAGE_SM, Ahi, Alo, Bhi, m0, n0, BK, K, tid);
    CP_COMMIT();

    const int a_row = lane & 15;
    const int a_chi = lane >> 4;
    const int b_row = (lane & 7) + ((lane >> 4) << 3);
    const int b_chi = (lane >> 3) & 1;

    for (int it = 0; it < NIT; ++it) {
        CP_WAIT1();
        __syncthreads();
        if (it + 2 < NIT)
            load_stage(sb + ((it + 2) % 3) * STAGE_SM,
                       Ahi, Alo, Bhi, m0, n0, (it + 2) * BK, K, tid);
        CP_COMMIT();

        const uint32_t sA = sb + (it % 3) * STAGE_SM;
        const uint32_t sB = sA + 2 * TILE_SM;
#pragma unroll
        for (int kk = 0; kk < 2; kk++) {
            uint32_t ah[4][4], al[4][4], bh[2][4];
#pragma unroll
            for (int mt = 0; mt < 4; mt++) {
                const int r = wm * 64 + mt * 16 + a_row;
                const int c = kk * 2 + a_chi;
                const uint32_t aaddr = sA + r * 64 + (SWZ(r, c) << 4);
                ldsm_x4(ah[mt], aaddr);
                ldsm_x4(al[mt], aaddr + TILE_SM);
            }
#pragma unroll
            for (int ntp = 0; ntp < 2; ntp++) {
                const int r = wn * 32 + ntp * 16 + b_row;
                const int c = kk * 2 + b_chi;
                const uint32_t baddr = sB + r * 64 + (SWZ(r, c) << 4);
                ldsm_x4(bh[ntp], baddr);
            }
#pragma unroll
            for (int mt = 0; mt < 4; mt++)
#pragma unroll
                for (int nt = 0; nt < 4; nt++) {
                    const uint32_t* bhf = bh[nt >> 1] + (nt & 1) * 2;
                    mma_f16(acc[mt][nt], ah[mt], bhf);
                    mma_f16(acc[mt][nt], al[mt], bhf);
                }
        }
    }

    if (!EPI) {
#pragma unroll
        for (int mt = 0; mt < 4; mt++) {
            const int row = m0 + wm * 64 + mt * 16 + lr;
#pragma unroll
            for (int nt = 0; nt < 4; nt++) {
                const int col = n0 + wn * 32 + nt * 8 + (lane & 3) * 2;
                float2* p0 = (float2*)&C[(size_t)row * N + col];
                float2* p1 = (float2*)&C[(size_t)(row + 8) * N + col];
                *p0 = make_float2(acc[mt][nt][0], acc[mt][nt][1]);
                *p1 = make_float2(acc[mt][nt][2], acc[mt][nt][3]);
            }
        }
    } else {
        // regions: [0,NQ): Q hi+lo + rope; [NQ,NQ+NKV): K hi + rope; rest: V hi
        __half *Dh, *Dl = nullptr;
        int dstride, coff;
        bool dorope;
        if (n0 < NQ)            { Dh = Qh; Dl = Ql; dstride = NQ;  coff = 0;        dorope = true; }
        else if (n0 < NQ + NKV) { Dh = Kh;          dstride = NKV; coff = NQ;       dorope = true; }
        else                    { Dh = Vh;          dstride = NKV; coff = NQ + NKV; dorope = false; }
        const bool wlo = (n0 < NQ);
#pragma unroll
        for (int mt = 0; mt < 4; mt++) {
#pragma unroll
            for (int nt = 0; nt < 4; nt++) {
                const int col = n0 + wn * 32 + nt * 8 + (lane & 3) * 2;
                const int fi = (col & 127) >> 1;
#pragma unroll
                for (int r = 0; r < 2; r++) {
                    const int row = m0 + wm * 64 + mt * 16 + lr + 8 * r;
                    float x0 = acc[mt][nt][2 * r];
                    float x1 = acc[mt][nt][2 * r + 1];
                    float y0 = x0, y1 = x1;
                    if (dorope) {
                        const int s = row & (Sv - 1);
                        const float c  = __ldg(cs + s * 64 + fi);
                        const float sv = __ldg(sn + s * 64 + fi);
                        y0 = x0 * c - x1 * sv;
                        y1 = x0 * sv + x1 * c;
                    }
                    const uint32_t hw = pack2h(y0, y1);
                    const size_t o = (size_t)row * dstride + (col - coff);
                    *(uint32_t*)&Dh[o] = hw;
                    if (wlo) {
                        __half2 hb = *(__half2*)&hw;
                        *(uint32_t*)&Dl[o] =
                            pack2h(y0 - __half2float(hb.x), y1 - __half2float(hb.y));
                    }
                }
            }
        }
    }
}

// ---------------------------------------------------------------------------
// HMMA fp16 1-pass GEMM (WO projection): C = Ahi @ Bhi^T, fp32 out.
// Same skeleton, 2 tiles/stage (16KB), 48KB smem, 2 CTAs/SM.
// ---------------------------------------------------------------------------
#define STAGE1_SM  (2 * TILE_SM)       // 16384 B (Ahi, Bhi)
#define GEMM1_SMEM (3 * STAGE1_SM)     // 49152 B

__device__ __forceinline__ void load_stage1(
    uint32_t sbase,
    const __half* __restrict__ Ahi, const __half* __restrict__ Bhi,
    int m0, int n0, int k0, int K, int tid)
{
#pragma unroll
    for (int j = 0; j < 4; j++) {
        const int tile = j >> 1;              // 0:Ahi 1:Bhi
        const int cc = tid + (j & 1) * 256;
        const int row = cc >> 2;
        const int c16 = cc & 3;
        const uint32_t soff = sbase + tile * TILE_SM + row * 64 + (SWZ(row, c16) << 4);
        const __half* g = (tile == 0) ? Ahi : Bhi;
        const int grow = (tile == 0) ? (m0 + row) : (n0 + row);
        cp16(soff, g + (size_t)grow * K + k0 + c16 * 8);
    }
}

__global__ __launch_bounds__(256, 2) void gemm_hmma_x1(
    const __half* __restrict__ Ahi, const __half* __restrict__ Bhi,
    float* __restrict__ C, int N, int K)
{
    extern __shared__ char smem[];
    const uint32_t sb = smem_u32(smem);
    const int tid = threadIdx.x;
    const int wid = tid >> 5, lane = tid & 31;
    const int wm = wid & 1;
    const int wn = wid >> 1;
    const int lr = lane >> 2;
    const int m0 = blockIdx.y * BM, n0 = blockIdx.x * BN;

    float acc[4][4][4];
#pragma unroll
    for (int mt = 0; mt < 4; mt++)
#pragma unroll
        for (int nt = 0; nt < 4; nt++)
#pragma unroll
            for (int r = 0; r < 4; r++) acc[mt][nt][r] = 0.f;

    const int NIT = K / BK;

    load_stage1(sb,             Ahi, Bhi, m0, n0, 0,  K, tid);
    CP_COMMIT();
    load_stage1(sb + STAGE1_SM, Ahi, Bhi, m0, n0, BK, K, tid);
    CP_COMMIT();

    const int a_row = lane & 15;
    const int a_chi = lane >> 4;
    const int b_row = (lane & 7) + ((lane >> 4) << 3);
    const int b_chi = (lane >> 3) & 1;

    for (int it = 0; it < NIT; ++it) {
        CP_WAIT1();
        __syncthreads();
        if (it + 2 < NIT)
            load_stage1(sb + ((it + 2) % 3) * STAGE1_SM,
                        Ahi, Bhi, m0, n0, (it + 2) * BK, K, tid);
        CP_COMMIT();

        const uint32_t sA = sb + (it % 3) * STAGE1_SM;
        const uint32_t sB = sA + TILE_SM;
#pragma unroll
        for (int kk = 0; kk < 2; kk++) {
            uint32_t ah[4][4], bh[2][4];
#pragma unroll
            for (int mt = 0; mt < 4; mt++) {
                const int r = wm * 64 + mt * 16 + a_row;
                const int c = kk * 2 + a_chi;
                ldsm_x4(ah[mt], sA + r * 64 + (SWZ(r, c) << 4));
            }
#pragma unroll
            for (int ntp = 0; ntp < 2; ntp++) {
                const int r = wn * 32 + ntp * 16 + b_row;
                const int c = kk * 2 + b_chi;
                ldsm_x4(bh[ntp], sB + r * 64 + (SWZ(r, c) << 4));
            }
#pragma unroll
            for (int mt = 0; mt < 4; mt++)
#pragma unroll
                for (int nt = 0; nt < 4; nt++)
                    mma_f16(acc[mt][nt], ah[mt], bh[nt >> 1] + (nt & 1) * 2);
        }
    }

#pragma unroll
    for (int mt = 0; mt < 4; mt++) {
        const int row = m0 + wm * 64 + mt * 16 + lr;
#pragma unroll
        for (int nt = 0; nt < 4; nt++) {
            const int col = n0 + wn * 32 + nt * 8 + (lane & 3) * 2;
            float2* p0 = (float2*)&C[(size_t)row * N + col];
            float2* p1 = (float2*)&C[(size_t)(row + 8) * N + col];
            *p0 = make_float2(acc[mt][nt][0], acc[mt][nt][1]);
            *p1 = make_float2(acc[mt][nt][2], acc[mt][nt][3]);
        }
    }
}

// ---------------------------------------------------------------------------
// HMMA flash attention, fp16 2-pass (R10, proven).
// CTA = 64 q-rows, 128 threads, K/V hi tiles of 32 rows double-buffered,
// Q hi+lo register-resident. ~70KB smem, 2 CTAs/SM, longest-first order.
// Epilogue writes att hi ONLY (WO is 1-pass now).
// ---------------------------------------------------------------------------
#define FROWB 272
#define FQ_HALF  (64 * FROWB)
#define FK_HALF  (32 * FROWB)
#define SM_KV    (2 * FQ_HALF)
#define KV_STAGE (2 * FK_HALF)
#define FLASH_SMEM (SM_KV + 2 * KV_STAGE)   // 69632

__device__ __forceinline__ void flash_load_kv(
    uint32_t sb, int stage,
    const __half* __restrict__ Kh, const __half* __restrict__ Vh,
    size_t gbase, int tid)
{
#pragma unroll
    for (int j = 0; j < 8; j++) {
        const int t = j >> 2;
        const int cc = tid + (j & 3) * 128;
        const int row = cc >> 4, c16 = cc & 15;
        const __half* g = (t == 0) ? Kh : Vh;
        const uint32_t soff = sb + SM_KV + stage * KV_STAGE + t * FK_HALF
                              + row * FROWB + c16 * 16;
        cp16(soff, g + gbase + (size_t)row * NKV + c16 * 8);
    }
}

__global__ __launch_bounds__(128, 2) void flash_hmma(
    const __half* __restrict__ Qh_g, const __half* __restrict__ Ql_g,
    const __half* __restrict__ Kh_g, const __half* __restrict__ Vh_g,
    __half* __restrict__ Oh)
{
    extern __shared__ char smem[];
    const uint32_t sb = smem_u32(smem);
    const int tid = threadIdx.x, w = tid >> 5, lane = tid & 31;
    const int lr = lane >> 2, lc = lane & 3;
    const int qb = gridDim.x - 1 - blockIdx.x;   // longest-first
    const int q0 = qb * 64, h = blockIdx.y, b = blockIdx.z;
    const int kvh = h >> 2;
    const float scale = 0.08838834764831845f;

    {
        const size_t gq = ((size_t)(b * Sv + q0)) * NQ + h * HDv;
#pragma unroll
        for (int j = 0; j < 16; j++) {
            const int hl = j >> 3;
            const int cc = tid + (j & 7) * 128;
            const int row = cc >> 4, c16 = cc & 15;
            const __half* g = hl ? Ql_g : Qh_g;
            cp16(sb + hl * FQ_HALF + row * FROWB + c16 * 16,
                 g + gq + (size_t)row * NQ + c16 * 8);
        }
    }
    CP_COMMIT();
    flash_load_kv(sb, 0, Kh_g, Vh_g, ((size_t)(b * Sv)) * NKV + kvh * HDv, tid);
    CP_COMMIT();

    const int a_row = lane & 15;
    const int a_cb  = (lane >> 4) << 4;
    const int b_row = (lane & 7) + ((lane >> 4) << 3);
    const int b_cb  = ((lane >> 3) & 1) << 4;

    CP_WAIT1();
    __syncthreads();
    uint32_t qh[8][4], ql[8][4];
#pragma unroll
    for (int kf = 0; kf < 8; kf++) {
        const uint32_t qaddr = sb + (w * 16 + a_row) * FROWB + kf * 32 + a_cb;
        ldsm_x4(qh[kf], qaddr);
        ldsm_x4(ql[kf], qaddr + FQ_HALF);
    }

    float o[16][4];
#pragma unroll
    for (int i = 0; i < 16; i++)
#pragma unroll
        for (int j = 0; j < 4; j++) o[i][j] = 0.f;
    float mrow[2] = {-1e30f, -1e30f};
    float lrow[2] = {0.f, 0.f};

    const int ktmax = 2 * qb + 1;
    for (int kt = 0; kt <= ktmax; ++kt) {
        CP_WAIT0();
        __syncthreads();
        if (kt < ktmax) {
            flash_load_kv(sb, (kt + 1) & 1, Kh_g, Vh_g,
                          ((size_t)(b * Sv + (kt + 1) * 32)) * NKV + kvh * HDv, tid);
            CP_COMMIT();
        }

        const int k0 = kt * 32;
        if (k0 > q0 + w * 16 + 15) continue;

        const uint32_t Kst = sb + SM_KV + (kt & 1) * KV_STAGE;
        const uint32_t Vst = Kst + FK_HALF;

        float s[4][4];
#pragma unroll
        for (int nf = 0; nf < 4; nf++)
#pragma unroll
            for (int r = 0; r < 4; r++) s[nf][r] = 0.f;

#pragma unroll
        for (int kf = 0; kf < 8; kf++) {
#pragma unroll
            for (int nfp = 0; nfp < 2; nfp++) {
                const uint32_t kaddr = Kst + (nfp * 16 + b_row) * FROWB + kf * 32 + b_cb;
                uint32_t bh4[4];
                ldsm_x4(bh4, kaddr);
                mma_f16(s[2 * nfp],     qh[kf], bh4);
                mma_f16(s[2 * nfp],     ql[kf], bh4);
                mma_f16(s[2 * nfp + 1], qh[kf], bh4 + 2);
                mma_f16(s[2 * nfp + 1], ql[kf], bh4 + 2);
            }
        }

        const bool diag = (k0 + 31 > q0 + w * 16);
#pragma unroll
        for (int r = 0; r < 2; r++) {
            const int qrow = q0 + w * 16 + lr + 8 * r;
            float mx = -1e30f;
#pragma unroll
            for (int nf = 0; nf < 4; nf++) {
                float v0 = s[nf][2 * r] * scale;
                float v1 = s[nf][2 * r + 1] * scale;
                if (diag) {
                    const int col = k0 + nf * 8 + lc * 2;
                    if (col > qrow) v0 = -1e30f;
                    if (col + 1 > qrow) v1 = -1e30f;
                }
                s[nf][2 * r] = v0;
                s[nf][2 * r + 1] = v1;
                mx = fmaxf(mx, fmaxf(v0, v1));
            }
            mx = fmaxf(mx, __shfl_xor_sync(0xffffffffu, mx, 1));
            mx = fmaxf(mx, __shfl_xor_sync(0xffffffffu, mx, 2));
            const float m_new = fmaxf(mrow[r], mx);
            const float alpha = __expf(mrow[r] - m_new);
            mrow[r] = m_new;
            float sum = 0.f;
#pragma unroll
            for (int nf = 0; nf < 4; nf++) {
                float p0 = __expf(s[nf][2 * r] - m_new);
                float p1 = __expf(s[nf][2 * r + 1] - m_new);
                s[nf][2 * r] = p0;
                s[nf][2 * r + 1] = p1;
                sum += p0 + p1;
            }
            sum += __shfl_xor_sync(0xffffffffu, sum, 1);
            sum += __shfl_xor_sync(0xffffffffu, sum, 2);
            lrow[r] = lrow[r] * alpha + sum;
#pragma unroll
            for (int nf2 = 0; nf2 < 16; nf2++) {
                o[nf2][2 * r] *= alpha;
                o[nf2][2 * r + 1] *= alpha;
            }
        }

        uint32_t phi[2][4], plo[2][4];
#pragma unroll
        for (int kf2 = 0; kf2 < 2; kf2++) {
#pragma unroll
            for (int m = 0; m < 2; m++) {
                const int nf = 2 * kf2 + m;
                float x0 = s[nf][0], x1 = s[nf][1], x2 = s[nf][2], x3 = s[nf][3];
                uint32_t h01 = pack2h(x0, x1), h23 = pack2h(x2, x3);
                phi[kf2][2 * m]     = h01;
                phi[kf2][2 * m + 1] = h23;
                __half2 b01 = *(__half2*)&h01;
                __half2 b23 = *(__half2*)&h23;
                plo[kf2][2 * m]     = pack2h(x0 - __half2float(b01.x),
                                             x1 - __half2float(b01.y));
                plo[kf2][2 * m + 1] = pack2h(x2 - __half2float(b23.x),
                                             x3 - __half2float(b23.y));
            }
        }

#pragma unroll
        for (int kf2 = 0; kf2 < 2; kf2++) {
#pragma unroll
            for (int nfp = 0; nfp < 8; nfp++) {
                const uint32_t va = Vst + (kf2 * 16 + (lane & 15)) * FROWB
                                    + (nfp * 16 + ((lane >> 4) << 3)) * 2;
                uint32_t bh4[4];
                ldsm_x4_t(bh4, va);
                mma_f16(o[2 * nfp],     phi[kf2], bh4);
                mma_f16(o[2 * nfp],     plo[kf2], bh4);
                mma_f16(o[2 * nfp + 1], phi[kf2], bh4 + 2);
                mma_f16(o[2 * nfp + 1], plo[kf2], bh4 + 2);
            }
        }
    }

    // ---- epilogue: write att hi only ----
#pragma unroll
    for (int r = 0; r < 2; r++) {
        const float inv = 1.f / lrow[r];
        const int row = q0 + w * 16 + lr + 8 * r;
        const size_t base = ((size_t)(b * Sv + row)) * NQ + h * HDv + lc * 2;
#pragma unroll
        for (int nf2 = 0; nf2 < 16; nf2++) {
            *(uint32_t*)&Oh[base + nf2 * 8] =
                pack2h(o[nf2][2 * r] * inv, o[nf2][2 * r + 1] * inv);
        }
    }
}

// ---------------------------------------------------------------------------
// Launch. Inputs: 0=x 1=cos 2=sin 3=positions 4=mask 5=wq 6=wk 7=wv 8=wo
// ---------------------------------------------------------------------------
extern "C" void kernel_launch(void* const* d_in, const int* in_sizes, int n_in,
                              void* d_out, int out_size)
{
    const float* x  = (const float*)d_in[0];
    const float* fc = (const float*)d_in[1];
    const float* fs = (const float*)d_in[2];
    const float* wq = (const float*)d_in[5];
    const float* wk = (const float*)d_in[6];
    const float* wv = (const float*)d_in[7];
    const float* wo = (const float*)d_in[8];
    float* out = (float*)d_out;

    __half *xh, *xl, *wh, *oh, *ah, *qrh, *qrl, *krh, *vsh;
    cudaGetSymbolAddress((void**)&xh, g_x_hi);    cudaGetSymbolAddress((void**)&xl, g_x_lo);
    cudaGetSymbolAddress((void**)&wh, g_wqkv_hi);
    cudaGetSymbolAddress((void**)&oh, g_wo_hi);
    cudaGetSymbolAddress((void**)&ah, g_at_hi);
    cudaGetSymbolAddress((void**)&qrh, g_qr_hi);  cudaGetSymbolAddress((void**)&qrl, g_qr_lo);
    cudaGetSymbolAddress((void**)&krh, g_kr_hi);
    cudaGetSymbolAddress((void**)&vsh, g_vs_hi);

    // conversions: x -> hi+lo; weights -> hi only (concatenated wqkv)
    {
        long n4;
        n4 = (long)Mv * Dv / 4;
        cvt_split<<<(unsigned)((n4 + 255) / 256), 256>>>(x, xh, xl, n4);
        n4 = (long)NQ * Dv / 4;
        cvt_hi<<<(unsigned)((n4 + 255) / 256), 256>>>(wq, wh, n4);
        n4 = (long)NKV * Dv / 4;
        cvt_hi<<<(unsigned)((n4 + 255) / 256), 256>>>(wk, wh + (size_t)NQ * Dv, n4);
        cvt_hi<<<(unsigned)((n4 + 255) / 256), 256>>>(wv, wh + (size_t)(NQ + NKV) * Dv, n4);
        n4 = (long)Dv * NQ / 4;
        cvt_hi<<<(unsigned)((n4 + 255) / 256), 256>>>(wo, oh, n4);
    }

    cudaFuncSetAttribute(gemm_hmma_x2<true>,
                         cudaFuncAttributeMaxDynamicSharedMemorySize, GEMM_SMEM);
    cudaFuncSetAttribute(gemm_hmma_x1,
                         cudaFuncAttributeMaxDynamicSharedMemorySize, GEMM1_SMEM);

    // Fused QKV projection + RoPE + split (2-pass)
    gemm_hmma_x2<true><<<dim3(NQKV / BN, Mv / BM), 256, GEMM_SMEM>>>(
        xh, xl, wh, nullptr,
        qrh, qrl, krh, vsh, fc, fs, NQKV, Dv);

    // Flash attention (fp16 2-pass, 2 CTAs/SM, longest-first)
    cudaFuncSetAttribute(flash_hmma, cudaFuncAttributeMaxDynamicSharedMemorySize, FLASH_SMEM);
    flash_hmma<<<dim3(Sv / 64, Hv, Bv), 128, FLASH_SMEM>>>(
        qrh, qrl, krh, vsh, ah);

    // Output projection (1-pass)
    gemm_hmma_x1<<<dim3(NQ / BN, Mv / BM), 256, GEMM1_SMEM>>>(
        ah, oh, out, NQ, Dv);
}

// round 13
// speedup vs baseline: 1.6602x; 1.3008x over previous
#include <cuda_runtime.h>
#include <cuda_fp16.h>
#include <cstdint>
#include <math.h>

// Problem constants
#define Bv   2
#define Sv   2048
#define Dv   4096
#define Hv   32
#define KVHv 8
#define HDv  128
#define Mv   (Bv * Sv)       // 4096
#define NQ   (Hv * HDv)      // 4096
#define NKV  (KVHv * HDv)    // 1024
#define NQKV (NQ + 2 * NKV)  // 6144

// fp16 scratch
__device__ __half g_x_hi[(size_t)Mv * Dv];
__device__ __half g_wqkv_hi[(size_t)NQKV * Dv];
__device__ __half g_wo_hi[(size_t)Dv * NQ];
__device__ __half g_at_hi[(size_t)Mv * NQ];
__device__ __half g_qr_hi[(size_t)Mv * NQ],  g_qr_lo[(size_t)Mv * NQ];
__device__ __half g_kr_hi[(size_t)Mv * NKV];
__device__ __half g_vs_hi[(size_t)Mv * NKV];

// ---------------------------------------------------------------------------
// Helpers (compute_103-safe)
// ---------------------------------------------------------------------------
__device__ __forceinline__ uint32_t smem_u32(const void* p) {
    uint32_t a;
    asm("{ .reg .u64 t; cvta.to.shared.u64 t, %1; cvt.u32.u64 %0, t; }" : "=r"(a) : "l"(p));
    return a;
}
__device__ __forceinline__ void cp16(uint32_t dst, const void* src) {
    asm volatile("cp.async.cg.shared.global [%0], [%1], 16;" :: "r"(dst), "l"(src));
}
#define CP_COMMIT() asm volatile("cp.async.commit_group;" ::: "memory")
#define CP_WAIT1()  asm volatile("cp.async.wait_group 1;" ::: "memory")
#define CP_WAIT0()  asm volatile("cp.async.wait_group 0;" ::: "memory")

__device__ __forceinline__ void mma_f16(float* c, const uint32_t* a, const uint32_t* b) {
    asm volatile("mma.sync.aligned.m16n8k16.row.col.f32.f16.f16.f32 "
        "{%0,%1,%2,%3}, {%4,%5,%6,%7}, {%8,%9}, {%0,%1,%2,%3};"
        : "+f"(c[0]), "+f"(c[1]), "+f"(c[2]), "+f"(c[3])
        : "r"(a[0]), "r"(a[1]), "r"(a[2]), "r"(a[3]), "r"(b[0]), "r"(b[1]));
}
__device__ __forceinline__ void ldsm_x4(uint32_t* r, uint32_t addr) {
    asm volatile("ldmatrix.sync.aligned.m8n8.x4.shared.b16 {%0,%1,%2,%3}, [%4];"
        : "=r"(r[0]), "=r"(r[1]), "=r"(r[2]), "=r"(r[3]) : "r"(addr));
}
__device__ __forceinline__ void ldsm_x4_t(uint32_t* r, uint32_t addr) {
    asm volatile("ldmatrix.sync.aligned.m8n8.x4.trans.shared.b16 {%0,%1,%2,%3}, [%4];"
        : "=r"(r[0]), "=r"(r[1]), "=r"(r[2]), "=r"(r[3]) : "r"(addr));
}
__device__ __forceinline__ uint32_t pack2h(float x, float y) {
    __half2 t = __floats2half2_rn(x, y);
    return *(uint32_t*)&t;
}

// ---------------------------------------------------------------------------
// fp32 -> fp16 (round-to-nearest)
// ---------------------------------------------------------------------------
__global__ void cvt_hi(const float* __restrict__ in,
                       __half* __restrict__ hi, long n4) {
    long i = (long)blockIdx.x * blockDim.x + threadIdx.x;
    if (i >= n4) return;
    float4 v = ((const float4*)in)[i];
    ((__half2*)hi)[i * 2]     = __floats2half2_rn(v.x, v.y);
    ((__half2*)hi)[i * 2 + 1] = __floats2half2_rn(v.z, v.w);
}

// ---------------------------------------------------------------------------
// HMMA fp16 1-pass GEMM: C = Ahi @ Bhi^T.
// 128x128 CTA tile, BK=32, 3-stage pipeline (Ahi,Bhi = 16KB/stage),
// 48KB smem, 2 CTAs/SM, swizzled 64B rows, ldmatrix loads.
// EPI=1: fused RoPE + split epilogue (Q: hi+lo; K,V: hi); EPI=0: fp32 C.
// ---------------------------------------------------------------------------
#define BM 128
#define BN 128
#define BK 32
#define TILE_SM   (128 * 64)          // 8192 B
#define STAGE_SM  (2 * TILE_SM)       // 16384 B (Ahi, Bhi)
#define GEMM_SMEM (3 * STAGE_SM)      // 49152 B
#define SWZ(r, c16) ((c16) ^ (((r) >> 1) & 3))

__device__ __forceinline__ void load_stage(
    uint32_t sbase,
    const __half* __restrict__ Ahi, const __half* __restrict__ Bhi,
    int m0, int n0, int k0, int K, int tid)
{
#pragma unroll
    for (int j = 0; j < 4; j++) {
        const int tile = j >> 1;              // 0:Ahi 1:Bhi
        const int cc = tid + (j & 1) * 256;   // 0..511 within tile
        const int row = cc >> 2;
        const int c16 = cc & 3;
        const uint32_t soff = sbase + tile * TILE_SM + row * 64 + (SWZ(row, c16) << 4);
        const __half* g = (tile == 0) ? Ahi : Bhi;
        const int grow = (tile == 0) ? (m0 + row) : (n0 + row);
        cp16(soff, g + (size_t)grow * K + k0 + c16 * 8);
    }
}

template <bool EPI>
__global__ __launch_bounds__(256, 2) void gemm_hmma_x1(
    const __half* __restrict__ Ahi, const __half* __restrict__ Bhi,
    float* __restrict__ C,
    __half* __restrict__ Qh, __half* __restrict__ Ql,
    __half* __restrict__ Kh, __half* __restrict__ Vh,
    const float* __restrict__ cs, const float* __restrict__ sn,
    int N, int K)
{
    extern __shared__ char smem[];
    const uint32_t sb = smem_u32(smem);
    const int tid = threadIdx.x;
    const int wid = tid >> 5, lane = tid & 31;
    const int wm = wid & 1;
    const int wn = wid >> 1;
    const int lr = lane >> 2;
    const int m0 = blockIdx.y * BM, n0 = blockIdx.x * BN;

    float acc[4][4][4];
#pragma unroll
    for (int mt = 0; mt < 4; mt++)
#pragma unroll
        for (int nt = 0; nt < 4; nt++)
#pragma unroll
            for (int r = 0; r < 4; r++) acc[mt][nt][r] = 0.f;

    const int NIT = K / BK;

    load_stage(sb,            Ahi, Bhi, m0, n0, 0,  K, tid);
    CP_COMMIT();
    load_stage(sb + STAGE_SM, Ahi, Bhi, m0, n0, BK, K, tid);
    CP_COMMIT();

    const int a_row = lane & 15;
    const int a_chi = lane >> 4;
    const int b_row = (lane & 7) + ((lane >> 4) << 3);
    const int b_chi = (lane >> 3) & 1;

    for (int it = 0; it < NIT; ++it) {
        CP_WAIT1();
        __syncthreads();
        if (it + 2 < NIT)
            load_stage(sb + ((it + 2) % 3) * STAGE_SM,
                       Ahi, Bhi, m0, n0, (it + 2) * BK, K, tid);
        CP_COMMIT();   // always commit to keep group counting fixed

        const uint32_t sA = sb + (it % 3) * STAGE_SM;
        const uint32_t sB = sA + TILE_SM;
#pragma unroll
        for (int kk = 0; kk < 2; kk++) {
            uint32_t ah[4][4], bh[2][4];
#pragma unroll
            for (int mt = 0; mt < 4; mt++) {
                const int r = wm * 64 + mt * 16 + a_row;
                const int c = kk * 2 + a_chi;
                ldsm_x4(ah[mt], sA + r * 64 + (SWZ(r, c) << 4));
            }
#pragma unroll
            for (int ntp = 0; ntp < 2; ntp++) {
                const int r = wn * 32 + ntp * 16 + b_row;
                const int c = kk * 2 + b_chi;
                ldsm_x4(bh[ntp], sB + r * 64 + (SWZ(r, c) << 4));
            }
#pragma unroll
            for (int mt = 0; mt < 4; mt++)
#pragma unroll
                for (int nt = 0; nt < 4; nt++)
                    mma_f16(acc[mt][nt], ah[mt], bh[nt >> 1] + (nt & 1) * 2);
        }
    }

    if (!EPI) {
#pragma unroll
        for (int mt = 0; mt < 4; mt++) {
            const int row = m0 + wm * 64 + mt * 16 + lr;
#pragma unroll
            for (int nt = 0; nt < 4; nt++) {
                const int col = n0 + wn * 32 + nt * 8 + (lane & 3) * 2;
                float2* p0 = (float2*)&C[(size_t)row * N + col];
                float2* p1 = (float2*)&C[(size_t)(row + 8) * N + col];
                *p0 = make_float2(acc[mt][nt][0], acc[mt][nt][1]);
                *p1 = make_float2(acc[mt][nt][2], acc[mt][nt][3]);
            }
        }
    } else {
        // regions: [0,NQ): Q hi+lo + rope; [NQ,NQ+NKV): K hi + rope; rest: V hi
        __half *Dh, *Dl = nullptr;
        int dstride, coff;
        bool dorope;
        if (n0 < NQ)            { Dh = Qh; Dl = Ql; dstride = NQ;  coff = 0;        dorope = true; }
        else if (n0 < NQ + NKV) { Dh = Kh;          dstride = NKV; coff = NQ;       dorope = true; }
        else                    { Dh = Vh;          dstride = NKV; coff = NQ + NKV; dorope = false; }
        const bool wlo = (n0 < NQ);
#pragma unroll
        for (int mt = 0; mt < 4; mt++) {
#pragma unroll
            for (int nt = 0; nt < 4; nt++) {
                const int col = n0 + wn * 32 + nt * 8 + (lane & 3) * 2;
                const int fi = (col & 127) >> 1;
#pragma unroll
                for (int r = 0; r < 2; r++) {
                    const int row = m0 + wm * 64 + mt * 16 + lr + 8 * r;
                    float x0 = acc[mt][nt][2 * r];
                    float x1 = acc[mt][nt][2 * r + 1];
                    float y0 = x0, y1 = x1;
                    if (dorope) {
                        const int s = row & (Sv - 1);
                        const float c  = __ldg(cs + s * 64 + fi);
                        const float sv = __ldg(sn + s * 64 + fi);
                        y0 = x0 * c - x1 * sv;
                        y1 = x0 * sv + x1 * c;
                    }
                    const uint32_t hw = pack2h(y0, y1);
                    const size_t o = (size_t)row * dstride + (col - coff);
                    *(uint32_t*)&Dh[o] = hw;
                    if (wlo) {
                        __half2 hb = *(__half2*)&hw;
                        *(uint32_t*)&Dl[o] =
                            pack2h(y0 - __half2float(hb.x), y1 - __half2float(hb.y));
                    }
                }
            }
        }
    }
}

// ---------------------------------------------------------------------------
// HMMA flash attention, fp16 2-pass (proven R12).
// CTA = 64 q-rows, 128 threads, K/V hi tiles of 32 rows double-buffered,
// Q hi+lo register-resident. ~70KB smem, 2 CTAs/SM, longest-first order.
// ---------------------------------------------------------------------------
#define FROWB 272
#define FQ_HALF  (64 * FROWB)
#define FK_HALF  (32 * FROWB)
#define SM_KV    (2 * FQ_HALF)
#define KV_STAGE (2 * FK_HALF)
#define FLASH_SMEM (SM_KV + 2 * KV_STAGE)   // 69632

__device__ __forceinline__ void flash_load_kv(
    uint32_t sb, int stage,
    const __half* __restrict__ Kh, const __half* __restrict__ Vh,
    size_t gbase, int tid)
{
#pragma unroll
    for (int j = 0; j < 8; j++) {
        const int t = j >> 2;
        const int cc = tid + (j & 3) * 128;
        const int row = cc >> 4, c16 = cc & 15;
        const __half* g = (t == 0) ? Kh : Vh;
        const uint32_t soff = sb + SM_KV + stage * KV_STAGE + t * FK_HALF
                              + row * FROWB + c16 * 16;
        cp16(soff, g + gbase + (size_t)row * NKV + c16 * 8);
    }
}

__global__ __launch_bounds__(128, 2) void flash_hmma(
    const __half* __restrict__ Qh_g, const __half* __restrict__ Ql_g,
    const __half* __restrict__ Kh_g, const __half* __restrict__ Vh_g,
    __half* __restrict__ Oh)
{
    extern __shared__ char smem[];
    const uint32_t sb = smem_u32(smem);
    const int tid = threadIdx.x, w = tid >> 5, lane = tid & 31;
    const int lr = lane >> 2, lc = lane & 3;
    const int qb = gridDim.x - 1 - blockIdx.x;   // longest-first
    const int q0 = qb * 64, h = blockIdx.y, b = blockIdx.z;
    const int kvh = h >> 2;
    const float scale = 0.08838834764831845f;

    {
        const size_t gq = ((size_t)(b * Sv + q0)) * NQ + h * HDv;
#pragma unroll
        for (int j = 0; j < 16; j++) {
            const int hl = j >> 3;
            const int cc = tid + (j & 7) * 128;
            const int row = cc >> 4, c16 = cc & 15;
            const __half* g = hl ? Ql_g : Qh_g;
            cp16(sb + hl * FQ_HALF + row * FROWB + c16 * 16,
                 g + gq + (size_t)row * NQ + c16 * 8);
        }
    }
    CP_COMMIT();
    flash_load_kv(sb, 0, Kh_g, Vh_g, ((size_t)(b * Sv)) * NKV + kvh * HDv, tid);
    CP_COMMIT();

    const int a_row = lane & 15;
    const int a_cb  = (lane >> 4) << 4;
    const int b_row = (lane & 7) + ((lane >> 4) << 3);
    const int b_cb  = ((lane >> 3) & 1) << 4;

    CP_WAIT1();
    __syncthreads();
    uint32_t qh[8][4], ql[8][4];
#pragma unroll
    for (int kf = 0; kf < 8; kf++) {
        const uint32_t qaddr = sb + (w * 16 + a_row) * FROWB + kf * 32 + a_cb;
        ldsm_x4(qh[kf], qaddr);
        ldsm_x4(ql[kf], qaddr + FQ_HALF);
    }

    float o[16][4];
#pragma unroll
    for (int i = 0; i < 16; i++)
#pragma unroll
        for (int j = 0; j < 4; j++) o[i][j] = 0.f;
    float mrow[2] = {-1e30f, -1e30f};
    float lrow[2] = {0.f, 0.f};

    const int ktmax = 2 * qb + 1;
    for (int kt = 0; kt <= ktmax; ++kt) {
        CP_WAIT0();
        __syncthreads();
        if (kt < ktmax) {
            flash_load_kv(sb, (kt + 1) & 1, Kh_g, Vh_g,
                          ((size_t)(b * Sv + (kt + 1) * 32)) * NKV + kvh * HDv, tid);
            CP_COMMIT();
        }

        const int k0 = kt * 32;
        if (k0 > q0 + w * 16 + 15) continue;

        const uint32_t Kst = sb + SM_KV + (kt & 1) * KV_STAGE;
        const uint32_t Vst = Kst + FK_HALF;

        float s[4][4];
#pragma unroll
        for (int nf = 0; nf < 4; nf++)
#pragma unroll
            for (int r = 0; r < 4; r++) s[nf][r] = 0.f;

#pragma unroll
        for (int kf = 0; kf < 8; kf++) {
#pragma unroll
            for (int nfp = 0; nfp < 2; nfp++) {
                const uint32_t kaddr = Kst + (nfp * 16 + b_row) * FROWB + kf * 32 + b_cb;
                uint32_t bh4[4];
                ldsm_x4(bh4, kaddr);
                mma_f16(s[2 * nfp],     qh[kf], bh4);
                mma_f16(s[2 * nfp],     ql[kf], bh4);
                mma_f16(s[2 * nfp + 1], qh[kf], bh4 + 2);
                mma_f16(s[2 * nfp + 1], ql[kf], bh4 + 2);
            }
        }

        const bool diag = (k0 + 31 > q0 + w * 16);
#pragma unroll
        for (int r = 0; r < 2; r++) {
            const int qrow = q0 + w * 16 + lr + 8 * r;
            float mx = -1e30f;
#pragma unroll
            for (int nf = 0; nf < 4; nf++) {
                float v0 = s[nf][2 * r] * scale;
                float v1 = s[nf][2 * r + 1] * scale;
                if (diag) {
                    const int col = k0 + nf * 8 + lc * 2;
                    if (col > qrow) v0 = -1e30f;
                    if (col + 1 > qrow) v1 = -1e30f;
                }
                s[nf][2 * r] = v0;
                s[nf][2 * r + 1] = v1;
                mx = fmaxf(mx, fmaxf(v0, v1));
            }
            mx = fmaxf(mx, __shfl_xor_sync(0xffffffffu, mx, 1));
            mx = fmaxf(mx, __shfl_xor_sync(0xffffffffu, mx, 2));
            const float m_new = fmaxf(mrow[r], mx);
            const float alpha = __expf(mrow[r] - m_new);
            mrow[r] = m_new;
            float sum = 0.f;
#pragma unroll
            for (int nf = 0; nf < 4; nf++) {
                float p0 = __expf(s[nf][2 * r] - m_new);
                float p1 = __expf(s[nf][2 * r + 1] - m_new);
                s[nf][2 * r] = p0;
                s[nf][2 * r + 1] = p1;
                sum += p0 + p1;
            }
            sum += __shfl_xor_sync(0xffffffffu, sum, 1);
            sum += __shfl_xor_sync(0xffffffffu, sum, 2);
            lrow[r] = lrow[r] * alpha + sum;
#pragma unroll
            for (int nf2 = 0; nf2 < 16; nf2++) {
                o[nf2][2 * r] *= alpha;
                o[nf2][2 * r + 1] *= alpha;
            }
        }

        uint32_t phi[2][4], plo[2][4];
#pragma unroll
        for (int kf2 = 0; kf2 < 2; kf2++) {
#pragma unroll
            for (int m = 0; m < 2; m++) {
                const int nf = 2 * kf2 + m;
                float x0 = s[nf][0], x1 = s[nf][1], x2 = s[nf][2], x3 = s[nf][3];
                uint32_t h01 = pack2h(x0, x1), h23 = pack2h(x2, x3);
                phi[kf2][2 * m]     = h01;
                phi[kf2][2 * m + 1] = h23;
                __half2 b01 = *(__half2*)&h01;
                __half2 b23 = *(__half2*)&h23;
                plo[kf2][2 * m]     = pack2h(x0 - __half2float(b01.x),
                                             x1 - __half2float(b01.y));
                plo[kf2][2 * m + 1] = pack2h(x2 - __half2float(b23.x),
                                             x3 - __half2float(b23.y));
            }
        }

#pragma unroll
        for (int kf2 = 0; kf2 < 2; kf2++) {
#pragma unroll
            for (int nfp = 0; nfp < 8; nfp++) {
                const uint32_t va = Vst + (kf2 * 16 + (lane & 15)) * FROWB
                                    + (nfp * 16 + ((lane >> 4) << 3)) * 2;
                uint32_t bh4[4];
                ldsm_x4_t(bh4, va);
                mma_f16(o[2 * nfp],     phi[kf2], bh4);
                mma_f16(o[2 * nfp],     plo[kf2], bh4);
                mma_f16(o[2 * nfp + 1], phi[kf2], bh4 + 2);
                mma_f16(o[2 * nfp + 1], plo[kf2], bh4 + 2);
            }
        }
    }

    // ---- epilogue: write att hi only ----
#pragma unroll
    for (int r = 0; r < 2; r++) {
        const float inv = 1.f / lrow[r];
        const int row = q0 + w * 16 + lr + 8 * r;
        const size_t base = ((size_t)(b * Sv + row)) * NQ + h * HDv + lc * 2;
#pragma unroll
        for (int nf2 = 0; nf2 < 16; nf2++) {
            *(uint32_t*)&Oh[base + nf2 * 8] =
                pack2h(o[nf2][2 * r] * inv, o[nf2][2 * r + 1] * inv);
        }
    }
}

// ---------------------------------------------------------------------------
// Launch. Inputs: 0=x 1=cos 2=sin 3=positions 4=mask 5=wq 6=wk 7=wv 8=wo
// ---------------------------------------------------------------------------
extern "C" void kernel_launch(void* const* d_in, const int* in_sizes, int n_in,
                              void* d_out, int out_size)
{
    const float* x  = (const float*)d_in[0];
    const float* fc = (const float*)d_in[1];
    const float* fs = (const float*)d_in[2];
    const float* wq = (const float*)d_in[5];
    const float* wk = (const float*)d_in[6];
    const float* wv = (const float*)d_in[7];
    const float* wo = (const float*)d_in[8];
    float* out = (float*)d_out;

    __half *xh, *wh, *oh, *ah, *qrh, *qrl, *krh, *vsh;
    cudaGetSymbolAddress((void**)&xh, g_x_hi);
    cudaGetSymbolAddress((void**)&wh, g_wqkv_hi);
    cudaGetSymbolAddress((void**)&oh, g_wo_hi);
    cudaGetSymbolAddress((void**)&ah, g_at_hi);
    cudaGetSymbolAddress((void**)&qrh, g_qr_hi);  cudaGetSymbolAddress((void**)&qrl, g_qr_lo);
    cudaGetSymbolAddress((void**)&krh, g_kr_hi);
    cudaGetSymbolAddress((void**)&vsh, g_vs_hi);

    // conversions: everything -> fp16 hi (concatenated wqkv)
    {
        long n4;
        n4 = (long)Mv * Dv / 4;
        cvt_hi<<<(unsigned)((n4 + 255) / 256), 256>>>(x, xh, n4);
        n4 = (long)NQ * Dv / 4;
        cvt_hi<<<(unsigned)((n4 + 255) / 256), 256>>>(wq, wh, n4);
        n4 = (long)NKV * Dv / 4;
        cvt_hi<<<(unsigned)((n4 + 255) / 256), 256>>>(wk, wh + (size_t)NQ * Dv, n4);
        cvt_hi<<<(unsigned)((n4 + 255) / 256), 256>>>(wv, wh + (size_t)(NQ + NKV) * Dv, n4);
        n4 = (long)Dv * NQ / 4;
        cvt_hi<<<(unsigned)((n4 + 255) / 256), 256>>>(wo, oh, n4);
    }

    cudaFuncSetAttribute(gemm_hmma_x1<true>,
                         cudaFuncAttributeMaxDynamicSharedMemorySize, GEMM_SMEM);
    cudaFuncSetAttribute(gemm_hmma_x1<false>,
                         cudaFuncAttributeMaxDynamicSharedMemorySize, GEMM_SMEM);

    // Fused QKV projection + RoPE + split (1-pass)
    gemm_hmma_x1<true><<<dim3(NQKV / BN, Mv / BM), 256, GEMM_SMEM>>>(
        xh, wh, nullptr,
        qrh, qrl, krh, vsh, fc, fs, NQKV, Dv);

    // Flash attention (fp16 2-pass, 2 CTAs/SM, longest-first)
    cudaFuncSetAttribute(flash_hmma, cudaFuncAttributeMaxDynamicSharedMemorySize, FLASH_SMEM);
    flash_hmma<<<dim3(Sv / 64, Hv, Bv), 128, FLASH_SMEM>>>(
        qrh, qrl, krh, vsh, ah);

    // Output projection (1-pass)
    gemm_hmma_x1<false><<<dim3(NQ / BN, Mv / BM), 256, GEMM_SMEM>>>(
        ah, oh, out,
        nullptr, nullptr, nullptr, nullptr, nullptr, nullptr, NQ, Dv);
}

// round 14
// speedup vs baseline: 1.8839x; 1.1347x over previous
#include <cuda_runtime.h>
#include <cuda_fp16.h>
#include <cstdint>
#include <math.h>

// Problem constants
#define Bv   2
#define Sv   2048
#define Dv   4096
#define Hv   32
#define KVHv 8
#define HDv  128
#define Mv   (Bv * Sv)       // 4096
#define NQ   (Hv * HDv)      // 4096
#define NKV  (KVHv * HDv)    // 1024
#define NQKV (NQ + 2 * NKV)  // 6144

// fp16 scratch
__device__ __half g_x_hi[(size_t)Mv * Dv];
__device__ __half g_wqkv_hi[(size_t)NQKV * Dv];
__device__ __half g_wo_hi[(size_t)Dv * NQ];
__device__ __half g_at_hi[(size_t)Mv * NQ];
__device__ __half g_qr_hi[(size_t)Mv * NQ];
__device__ __half g_kr_hi[(size_t)Mv * NKV];
__device__ __half g_vs_hi[(size_t)Mv * NKV];

// ---------------------------------------------------------------------------
// Helpers (compute_103-safe)
// ---------------------------------------------------------------------------
__device__ __forceinline__ uint32_t smem_u32(const void* p) {
    uint32_t a;
    asm("{ .reg .u64 t; cvta.to.shared.u64 t, %1; cvt.u32.u64 %0, t; }" : "=r"(a) : "l"(p));
    return a;
}
__device__ __forceinline__ void cp16(uint32_t dst, const void* src) {
    asm volatile("cp.async.cg.shared.global [%0], [%1], 16;" :: "r"(dst), "l"(src));
}
#define CP_COMMIT() asm volatile("cp.async.commit_group;" ::: "memory")
#define CP_WAIT1()  asm volatile("cp.async.wait_group 1;" ::: "memory")
#define CP_WAIT0()  asm volatile("cp.async.wait_group 0;" ::: "memory")

__device__ __forceinline__ void mma_f16(float* c, const uint32_t* a, const uint32_t* b) {
    asm volatile("mma.sync.aligned.m16n8k16.row.col.f32.f16.f16.f32 "
        "{%0,%1,%2,%3}, {%4,%5,%6,%7}, {%8,%9}, {%0,%1,%2,%3};"
        : "+f"(c[0]), "+f"(c[1]), "+f"(c[2]), "+f"(c[3])
        : "r"(a[0]), "r"(a[1]), "r"(a[2]), "r"(a[3]), "r"(b[0]), "r"(b[1]));
}
__device__ __forceinline__ void ldsm_x4(uint32_t* r, uint32_t addr) {
    asm volatile("ldmatrix.sync.aligned.m8n8.x4.shared.b16 {%0,%1,%2,%3}, [%4];"
        : "=r"(r[0]), "=r"(r[1]), "=r"(r[2]), "=r"(r[3]) : "r"(addr));
}
__device__ __forceinline__ void ldsm_x4_t(uint32_t* r, uint32_t addr) {
    asm volatile("ldmatrix.sync.aligned.m8n8.x4.trans.shared.b16 {%0,%1,%2,%3}, [%4];"
        : "=r"(r[0]), "=r"(r[1]), "=r"(r[2]), "=r"(r[3]) : "r"(addr));
}
__device__ __forceinline__ uint32_t pack2h(float x, float y) {
    __half2 t = __floats2half2_rn(x, y);
    return *(uint32_t*)&t;
}

// ---------------------------------------------------------------------------
// fp32 -> fp16 (round-to-nearest)
// ---------------------------------------------------------------------------
__global__ void cvt_hi(const float* __restrict__ in,
                       __half* __restrict__ hi, long n4) {
    long i = (long)blockIdx.x * blockDim.x + threadIdx.x;
    if (i >= n4) return;
    float4 v = ((const float4*)in)[i];
    ((__half2*)hi)[i * 2]     = __floats2half2_rn(v.x, v.y);
    ((__half2*)hi)[i * 2 + 1] = __floats2half2_rn(v.z, v.w);
}

// ---------------------------------------------------------------------------
// HMMA fp16 1-pass GEMM: C = Ahi @ Bhi^T.  (proven R13 skeleton)
// 128x128 CTA tile, BK=32, 3-stage pipeline, 48KB smem, 2 CTAs/SM.
// EPI=1: fused RoPE + fp16 epilogue (Q,K: rope; V: plain); EPI=0: fp32 C.
// ---------------------------------------------------------------------------
#define BM 128
#define BN 128
#define BK 32
#define TILE_SM   (128 * 64)          // 8192 B
#define STAGE_SM  (2 * TILE_SM)       // 16384 B (Ahi, Bhi)
#define GEMM_SMEM (3 * STAGE_SM)      // 49152 B
#define SWZ(r, c16) ((c16) ^ (((r) >> 1) & 3))

__device__ __forceinline__ void load_stage(
    uint32_t sbase,
    const __half* __restrict__ Ahi, const __half* __restrict__ Bhi,
    int m0, int n0, int k0, int K, int tid)
{
#pragma unroll
    for (int j = 0; j < 4; j++) {
        const int tile = j >> 1;              // 0:Ahi 1:Bhi
        const int cc = tid + (j & 1) * 256;
        const int row = cc >> 2;
        const int c16 = cc & 3;
        const uint32_t soff = sbase + tile * TILE_SM + row * 64 + (SWZ(row, c16) << 4);
        const __half* g = (tile == 0) ? Ahi : Bhi;
        const int grow = (tile == 0) ? (m0 + row) : (n0 + row);
        cp16(soff, g + (size_t)grow * K + k0 + c16 * 8);
    }
}

template <bool EPI>
__global__ __launch_bounds__(256, 2) void gemm_hmma_x1(
    const __half* __restrict__ Ahi, const __half* __restrict__ Bhi,
    float* __restrict__ C,
    __half* __restrict__ Qh, __half* __restrict__ Kh, __half* __restrict__ Vh,
    const float* __restrict__ cs, const float* __restrict__ sn,
    int N, int K)
{
    extern __shared__ char smem[];
    const uint32_t sb = smem_u32(smem);
    const int tid = threadIdx.x;
    const int wid = tid >> 5, lane = tid & 31;
    const int wm = wid & 1;
    const int wn = wid >> 1;
    const int lr = lane >> 2;
    const int m0 = blockIdx.y * BM, n0 = blockIdx.x * BN;

    float acc[4][4][4];
#pragma unroll
    for (int mt = 0; mt < 4; mt++)
#pragma unroll
        for (int nt = 0; nt < 4; nt++)
#pragma unroll
            for (int r = 0; r < 4; r++) acc[mt][nt][r] = 0.f;

    const int NIT = K / BK;

    load_stage(sb,            Ahi, Bhi, m0, n0, 0,  K, tid);
    CP_COMMIT();
    load_stage(sb + STAGE_SM, Ahi, Bhi, m0, n0, BK, K, tid);
    CP_COMMIT();

    const int a_row = lane & 15;
    const int a_chi = lane >> 4;
    const int b_row = (lane & 7) + ((lane >> 4) << 3);
    const int b_chi = (lane >> 3) & 1;

    for (int it = 0; it < NIT; ++it) {
        CP_WAIT1();
        __syncthreads();
        if (it + 2 < NIT)
            load_stage(sb + ((it + 2) % 3) * STAGE_SM,
                       Ahi, Bhi, m0, n0, (it + 2) * BK, K, tid);
        CP_COMMIT();

        const uint32_t sA = sb + (it % 3) * STAGE_SM;
        const uint32_t sB = sA + TILE_SM;
#pragma unroll
        for (int kk = 0; kk < 2; kk++) {
            uint32_t ah[4][4], bh[2][4];
#pragma unroll
            for (int mt = 0; mt < 4; mt++) {
                const int r = wm * 64 + mt * 16 + a_row;
                const int c = kk * 2 + a_chi;
                ldsm_x4(ah[mt], sA + r * 64 + (SWZ(r, c) << 4));
            }
#pragma unroll
            for (int ntp = 0; ntp < 2; ntp++) {
                const int r = wn * 32 + ntp * 16 + b_row;
                const int c = kk * 2 + b_chi;
                ldsm_x4(bh[ntp], sB + r * 64 + (SWZ(r, c) << 4));
            }
#pragma unroll
            for (int mt = 0; mt < 4; mt++)
#pragma unroll
                for (int nt = 0; nt < 4; nt++)
                    mma_f16(acc[mt][nt], ah[mt], bh[nt >> 1] + (nt & 1) * 2);
        }
    }

    if (!EPI) {
#pragma unroll
        for (int mt = 0; mt < 4; mt++) {
            const int row = m0 + wm * 64 + mt * 16 + lr;
#pragma unroll
            for (int nt = 0; nt < 4; nt++) {
                const int col = n0 + wn * 32 + nt * 8 + (lane & 3) * 2;
                float2* p0 = (float2*)&C[(size_t)row * N + col];
                float2* p1 = (float2*)&C[(size_t)(row + 8) * N + col];
                *p0 = make_float2(acc[mt][nt][0], acc[mt][nt][1]);
                *p1 = make_float2(acc[mt][nt][2], acc[mt][nt][3]);
            }
        }
    } else {
        // regions: [0,NQ): Q + rope; [NQ,NQ+NKV): K + rope; rest: V
        __half* Dh;
        int dstride, coff;
        bool dorope;
        if (n0 < NQ)            { Dh = Qh; dstride = NQ;  coff = 0;        dorope = true; }
        else if (n0 < NQ + NKV) { Dh = Kh; dstride = NKV; coff = NQ;       dorope = true; }
        else                    { Dh = Vh; dstride = NKV; coff = NQ + NKV; dorope = false; }
#pragma unroll
        for (int mt = 0; mt < 4; mt++) {
#pragma unroll
            for (int nt = 0; nt < 4; nt++) {
                const int col = n0 + wn * 32 + nt * 8 + (lane & 3) * 2;
                const int fi = (col & 127) >> 1;
#pragma unroll
                for (int r = 0; r < 2; r++) {
                    const int row = m0 + wm * 64 + mt * 16 + lr + 8 * r;
                    float x0 = acc[mt][nt][2 * r];
                    float x1 = acc[mt][nt][2 * r + 1];
                    float y0 = x0, y1 = x1;
                    if (dorope) {
                        const int s = row & (Sv - 1);
                        const float c  = __ldg(cs + s * 64 + fi);
                        const float sv = __ldg(sn + s * 64 + fi);
                        y0 = x0 * c - x1 * sv;
                        y1 = x0 * sv + x1 * c;
                    }
                    *(uint32_t*)&Dh[(size_t)row * dstride + (col - coff)] =
                        pack2h(y0, y1);
                }
            }
        }
    }
}

// ---------------------------------------------------------------------------
// HMMA flash attention, fp16 1-pass (S = Qhi Khi^T, O = Phi Vhi).
// CTA = 64 q-rows, 128 threads, K/V tiles of 32 rows double-buffered,
// Q register-resident. 51KB smem, 3 CTAs/SM, longest-first order.
// ---------------------------------------------------------------------------
#define FROWB 272
#define FQ_SM    (64 * FROWB)          // 17408
#define FK_HALF  (32 * FROWB)          // 8704
#define SM_KV    FQ_SM
#define KV_STAGE (2 * FK_HALF)         // 17408 (Khi, Vhi)
#define FLASH_SMEM (SM_KV + 2 * KV_STAGE)   // 52224

__device__ __forceinline__ void flash_load_kv(
    uint32_t sb, int stage,
    const __half* __restrict__ Kh, const __half* __restrict__ Vh,
    size_t gbase, int tid)
{
#pragma unroll
    for (int j = 0; j < 8; j++) {
        const int t = j >> 2;                 // 0:Khi 1:Vhi
        const int cc = tid + (j & 3) * 128;
        const int row = cc >> 4, c16 = cc & 15;
        const __half* g = (t == 0) ? Kh : Vh;
        const uint32_t soff = sb + SM_KV + stage * KV_STAGE + t * FK_HALF
                              + row * FROWB + c16 * 16;
        cp16(soff, g + gbase + (size_t)row * NKV + c16 * 8);
    }
}

__global__ __launch_bounds__(128, 3) void flash_hmma(
    const __half* __restrict__ Qh_g,
    const __half* __restrict__ Kh_g, const __half* __restrict__ Vh_g,
    __half* __restrict__ Oh)
{
    extern __shared__ char smem[];
    const uint32_t sb = smem_u32(smem);
    const int tid = threadIdx.x, w = tid >> 5, lane = tid & 31;
    const int lr = lane >> 2, lc = lane & 3;
    const int qb = gridDim.x - 1 - blockIdx.x;   // longest-first
    const int q0 = qb * 64, h = blockIdx.y, b = blockIdx.z;
    const int kvh = h >> 2;
    const float scale = 0.08838834764831845f;

    // Stage Q (hi only)
    {
        const size_t gq = ((size_t)(b * Sv + q0)) * NQ + h * HDv;
#pragma unroll
        for (int j = 0; j < 8; j++) {
            const int cc = tid + j * 128;         // 0..1023
            const int row = cc >> 4, c16 = cc & 15;
            cp16(sb + row * FROWB + c16 * 16,
                 Qh_g + gq + (size_t)row * NQ + c16 * 8);
        }
    }
    CP_COMMIT();
    flash_load_kv(sb, 0, Kh_g, Vh_g, ((size_t)(b * Sv)) * NKV + kvh * HDv, tid);
    CP_COMMIT();

    const int a_row = lane & 15;
    const int a_cb  = (lane >> 4) << 4;
    const int b_row = (lane & 7) + ((lane >> 4) << 3);
    const int b_cb  = ((lane >> 3) & 1) << 4;

    // Q fragments -> registers (once)
    CP_WAIT1();
    __syncthreads();
    uint32_t qh[8][4];
#pragma unroll
    for (int kf = 0; kf < 8; kf++)
        ldsm_x4(qh[kf], sb + (w * 16 + a_row) * FROWB + kf * 32 + a_cb);

    float o[16][4];
#pragma unroll
    for (int i = 0; i < 16; i++)
#pragma unroll
        for (int j = 0; j < 4; j++) o[i][j] = 0.f;
    float mrow[2] = {-1e30f, -1e30f};
    float lrow[2] = {0.f, 0.f};

    const int ktmax = 2 * qb + 1;
    for (int kt = 0; kt <= ktmax; ++kt) {
        CP_WAIT0();
        __syncthreads();
        if (kt < ktmax) {
            flash_load_kv(sb, (kt + 1) & 1, Kh_g, Vh_g,
                          ((size_t)(b * Sv + (kt + 1) * 32)) * NKV + kvh * HDv, tid);
            CP_COMMIT();
        }

        const int k0 = kt * 32;
        if (k0 > q0 + w * 16 + 15) continue;

        const uint32_t Kst = sb + SM_KV + (kt & 1) * KV_STAGE;
        const uint32_t Vst = Kst + FK_HALF;

        // ---- S = Qhi Khi^T (1 pass) ----
        float s[4][4];
#pragma unroll
        for (int nf = 0; nf < 4; nf++)
#pragma unroll
            for (int r = 0; r < 4; r++) s[nf][r] = 0.f;

#pragma unroll
        for (int kf = 0; kf < 8; kf++) {
#pragma unroll
            for (int nfp = 0; nfp < 2; nfp++) {
                const uint32_t kaddr = Kst + (nfp * 16 + b_row) * FROWB + kf * 32 + b_cb;
                uint32_t bh4[4];
                ldsm_x4(bh4, kaddr);
                mma_f16(s[2 * nfp],     qh[kf], bh4);
                mma_f16(s[2 * nfp + 1], qh[kf], bh4 + 2);
            }
        }

        // ---- scale + causal mask + online softmax ----
        const bool diag = (k0 + 31 > q0 + w * 16);
#pragma unroll
        for (int r = 0; r < 2; r++) {
            const int qrow = q0 + w * 16 + lr + 8 * r;
            float mx = -1e30f;
#pragma unroll
            for (int nf = 0; nf < 4; nf++) {
                float v0 = s[nf][2 * r] * scale;
                float v1 = s[nf][2 * r + 1] * scale;
                if (diag) {
                    const int col = k0 + nf * 8 + lc * 2;
                    if (col > qrow) v0 = -1e30f;
                    if (col + 1 > qrow) v1 = -1e30f;
                }
                s[nf][2 * r] = v0;
                s[nf][2 * r + 1] = v1;
                mx = fmaxf(mx, fmaxf(v0, v1));
            }
            mx = fmaxf(mx, __shfl_xor_sync(0xffffffffu, mx, 1));
            mx = fmaxf(mx, __shfl_xor_sync(0xffffffffu, mx, 2));
            const float m_new = fmaxf(mrow[r], mx);
            const float alpha = __expf(mrow[r] - m_new);
            mrow[r] = m_new;
            float sum = 0.f;
#pragma unroll
            for (int nf = 0; nf < 4; nf++) {
                float p0 = __expf(s[nf][2 * r] - m_new);
                float p1 = __expf(s[nf][2 * r + 1] - m_new);
                s[nf][2 * r] = p0;
                s[nf][2 * r + 1] = p1;
                sum += p0 + p1;
            }
            sum += __shfl_xor_sync(0xffffffffu, sum, 1);
            sum += __shfl_xor_sync(0xffffffffu, sum, 2);
            lrow[r] = lrow[r] * alpha + sum;
#pragma unroll
            for (int nf2 = 0; nf2 < 16; nf2++) {
                o[nf2][2 * r] *= alpha;
                o[nf2][2 * r + 1] *= alpha;
            }
        }

        // ---- P -> fp16 A-fragments (hi only) ----
        uint32_t phi[2][4];
#pragma unroll
        for (int kf2 = 0; kf2 < 2; kf2++) {
#pragma unroll
            for (int m = 0; m < 2; m++) {
                const int nf = 2 * kf2 + m;
                phi[kf2][2 * m]     = pack2h(s[nf][0], s[nf][1]);
                phi[kf2][2 * m + 1] = pack2h(s[nf][2], s[nf][3]);
            }
        }

        // ---- O += Phi Vhi (1 pass), V via ldmatrix.trans ----
#pragma unroll
        for (int kf2 = 0; kf2 < 2; kf2++) {
#pragma unroll
            for (int nfp = 0; nfp < 8; nfp++) {
                const uint32_t va = Vst + (kf2 * 16 + (lane & 15)) * FROWB
                                    + (nfp * 16 + ((lane >> 4) << 3)) * 2;
                uint32_t bh4[4];
                ldsm_x4_t(bh4, va);
                mma_f16(o[2 * nfp],     phi[kf2], bh4);
                mma_f16(o[2 * nfp + 1], phi[kf2], bh4 + 2);
            }
        }
    }

    // ---- epilogue: write att hi ----
#pragma unroll
    for (int r = 0; r < 2; r++) {
        const float inv = 1.f / lrow[r];
        const int row = q0 + w * 16 + lr + 8 * r;
        const size_t base = ((size_t)(b * Sv + row)) * NQ + h * HDv + lc * 2;
#pragma unroll
        for (int nf2 = 0; nf2 < 16; nf2++) {
            *(uint32_t*)&Oh[base + nf2 * 8] =
                pack2h(o[nf2][2 * r] * inv, o[nf2][2 * r + 1] * inv);
        }
    }
}

// ---------------------------------------------------------------------------
// Launch. Inputs: 0=x 1=cos 2=sin 3=positions 4=mask 5=wq 6=wk 7=wv 8=wo
// ---------------------------------------------------------------------------
extern "C" void kernel_launch(void* const* d_in, const int* in_sizes, int n_in,
                              void* d_out, int out_size)
{
    const float* x  = (const float*)d_in[0];
    const float* fc = (const float*)d_in[1];
    const float* fs = (const float*)d_in[2];
    const float* wq = (const float*)d_in[5];
    const float* wk = (const float*)d_in[6];
    const float* wv = (const float*)d_in[7];
    const float* wo = (const float*)d_in[8];
    float* out = (float*)d_out;

    __half *xh, *wh, *oh, *ah, *qrh, *krh, *vsh;
    cudaGetSymbolAddress((void**)&xh, g_x_hi);
    cudaGetSymbolAddress((void**)&wh, g_wqkv_hi);
    cudaGetSymbolAddress((void**)&oh, g_wo_hi);
    cudaGetSymbolAddress((void**)&ah, g_at_hi);
    cudaGetSymbolAddress((void**)&qrh, g_qr_hi);
    cudaGetSymbolAddress((void**)&krh, g_kr_hi);
    cudaGetSymbolAddress((void**)&vsh, g_vs_hi);

    // conversions: everything -> fp16 (concatenated wqkv)
    {
        long n4;
        n4 = (long)Mv * Dv / 4;
        cvt_hi<<<(unsigned)((n4 + 255) / 256), 256>>>(x, xh, n4);
        n4 = (long)NQ * Dv / 4;
        cvt_hi<<<(unsigned)((n4 + 255) / 256), 256>>>(wq, wh, n4);
        n4 = (long)NKV * Dv / 4;
        cvt_hi<<<(unsigned)((n4 + 255) / 256), 256>>>(wk, wh + (size_t)NQ * Dv, n4);
        cvt_hi<<<(unsigned)((n4 + 255) / 256), 256>>>(wv, wh + (size_t)(NQ + NKV) * Dv, n4);
        n4 = (long)Dv * NQ / 4;
        cvt_hi<<<(unsigned)((n4 + 255) / 256), 256>>>(wo, oh, n4);
    }

    cudaFuncSetAttribute(gemm_hmma_x1<true>,
                         cudaFuncAttributeMaxDynamicSharedMemorySize, GEMM_SMEM);
    cudaFuncSetAttribute(gemm_hmma_x1<false>,
                         cudaFuncAttributeMaxDynamicSharedMemorySize, GEMM_SMEM);

    // Fused QKV projection + RoPE (1-pass)
    gemm_hmma_x1<true><<<dim3(NQKV / BN, Mv / BM), 256, GEMM_SMEM>>>(
        xh, wh, nullptr,
        qrh, krh, vsh, fc, fs, NQKV, Dv);

    // Flash attention (fp16 1-pass, 3 CTAs/SM, longest-first)
    cudaFuncSetAttribute(flash_hmma, cudaFuncAttributeMaxDynamicSharedMemorySize, FLASH_SMEM);
    flash_hmma<<<dim3(Sv / 64, Hv, Bv), 128, FLASH_SMEM>>>(
        qrh, krh, vsh, ah);

    // Output projection (1-pass)
    gemm_hmma_x1<false><<<dim3(NQ / BN, Mv / BM), 256, GEMM_SMEM>>>(
        ah, oh, out,
        nullptr, nullptr, nullptr, nullptr, nullptr, NQ, Dv);
}

// round 15
// speedup vs baseline: 1.9385x; 1.0290x over previous
#include <cuda_runtime.h>
#include <cuda_fp16.h>
#include <cstdint>
#include <math.h>

// Problem constants
#define Bv   2
#define Sv   2048
#define Dv   4096
#define Hv   32
#define KVHv 8
#define HDv  128
#define Mv   (Bv * Sv)       // 4096
#define NQ   (Hv * HDv)      // 4096
#define NKV  (KVHv * HDv)    // 1024
#define NQKV (NQ + 2 * NKV)  // 6144

// fp16 scratch
__device__ __half g_x_hi[(size_t)Mv * Dv];
__device__ __half g_wqkv_hi[(size_t)NQKV * Dv];
__device__ __half g_wo_hi[(size_t)Dv * NQ];
__device__ __half g_at_hi[(size_t)Mv * NQ];
__device__ __half g_qr_hi[(size_t)Mv * NQ];
__device__ __half g_kr_hi[(size_t)Mv * NKV];
__device__ __half g_vs_hi[(size_t)Mv * NKV];

// ---------------------------------------------------------------------------
// Helpers (compute_103-safe)
// ---------------------------------------------------------------------------
__device__ __forceinline__ uint32_t smem_u32(const void* p) {
    uint32_t a;
    asm("{ .reg .u64 t; cvta.to.shared.u64 t, %1; cvt.u32.u64 %0, t; }" : "=r"(a) : "l"(p));
    return a;
}
__device__ __forceinline__ void cp16(uint32_t dst, const void* src) {
    asm volatile("cp.async.cg.shared.global [%0], [%1], 16;" :: "r"(dst), "l"(src));
}
#define CP_COMMIT() asm volatile("cp.async.commit_group;" ::: "memory")
#define CP_WAIT1()  asm volatile("cp.async.wait_group 1;" ::: "memory")
#define CP_WAIT0()  asm volatile("cp.async.wait_group 0;" ::: "memory")

__device__ __forceinline__ void mma_f16(float* c, const uint32_t* a, const uint32_t* b) {
    asm volatile("mma.sync.aligned.m16n8k16.row.col.f32.f16.f16.f32 "
        "{%0,%1,%2,%3}, {%4,%5,%6,%7}, {%8,%9}, {%0,%1,%2,%3};"
        : "+f"(c[0]), "+f"(c[1]), "+f"(c[2]), "+f"(c[3])
        : "r"(a[0]), "r"(a[1]), "r"(a[2]), "r"(a[3]), "r"(b[0]), "r"(b[1]));
}
__device__ __forceinline__ void ldsm_x4(uint32_t* r, uint32_t addr) {
    asm volatile("ldmatrix.sync.aligned.m8n8.x4.shared.b16 {%0,%1,%2,%3}, [%4];"
        : "=r"(r[0]), "=r"(r[1]), "=r"(r[2]), "=r"(r[3]) : "r"(addr));
}
__device__ __forceinline__ void ldsm_x4_t(uint32_t* r, uint32_t addr) {
    asm volatile("ldmatrix.sync.aligned.m8n8.x4.trans.shared.b16 {%0,%1,%2,%3}, [%4];"
        : "=r"(r[0]), "=r"(r[1]), "=r"(r[2]), "=r"(r[3]) : "r"(addr));
}
__device__ __forceinline__ uint32_t pack2h(float x, float y) {
    __half2 t = __floats2half2_rn(x, y);
    return *(uint32_t*)&t;
}

// ---------------------------------------------------------------------------
// fp32 -> fp16 with 4x ILP (grid-strided, MLP=4)
// ---------------------------------------------------------------------------
__global__ void cvt_hi(const float* __restrict__ in,
                       __half* __restrict__ hi, long n4) {
    long stride = (long)gridDim.x * blockDim.x;
    long i = (long)blockIdx.x * blockDim.x + threadIdx.x;
    float4 v[4];
    bool ok[4];
    long idx = i;
#pragma unroll
    for (int j = 0; j < 4; j++, idx += stride) {
        ok[j] = (idx < n4);
        if (ok[j]) v[j] = ((const float4*)in)[idx];
    }
    idx = i;
#pragma unroll
    for (int j = 0; j < 4; j++, idx += stride) {
        if (ok[j]) {
            ((__half2*)hi)[idx * 2]     = __floats2half2_rn(v[j].x, v[j].y);
            ((__half2*)hi)[idx * 2 + 1] = __floats2half2_rn(v[j].z, v[j].w);
        }
    }
}
static inline unsigned cvt_grid(long n4) {
    return (unsigned)((n4 + 1023) / 1024);
}

// ---------------------------------------------------------------------------
// HMMA fp16 1-pass GEMM: C = Ahi @ Bhi^T.
// 128x128 CTA tile, BK=64 (halved sync count), 3-stage pipeline,
// 96KB smem, 2 CTAs/SM. 128B rows with SW128 swizzle, ldmatrix loads.
// EPI=1: fused RoPE + fp16 epilogue (Q,K: rope; V: plain); EPI=0: fp32 C.
// ---------------------------------------------------------------------------
#define BM 128
#define BN 128
#define BK 64
#define TILE_SM   (128 * 128)         // 16384 B (128 rows x 128B)
#define STAGE_SM  (2 * TILE_SM)       // 32768 B (Ahi, Bhi)
#define GEMM_SMEM (3 * STAGE_SM)      // 98304 B
// chunk swizzle within a 128B row: c8' = c8 ^ (row & 7)
#define SWZ8(r, c8) ((c8) ^ ((r) & 7))

__device__ __forceinline__ void load_stage(
    uint32_t sbase,
    const __half* __restrict__ Ahi, const __half* __restrict__ Bhi,
    int m0, int n0, int k0, int K, int tid)
{
#pragma unroll
    for (int j = 0; j < 8; j++) {
        const int tile = j >> 2;              // 0:Ahi 1:Bhi
        const int cc = tid + (j & 3) * 256;   // 0..1023 within tile
        const int row = cc >> 3;
        const int c8 = cc & 7;
        const uint32_t soff = sbase + tile * TILE_SM + row * 128 + (SWZ8(row, c8) << 4);
        const __half* g = (tile == 0) ? Ahi : Bhi;
        const int grow = (tile == 0) ? (m0 + row) : (n0 + row);
        cp16(soff, g + (size_t)grow * K + k0 + c8 * 8);
    }
}

template <bool EPI>
__global__ __launch_bounds__(256, 2) void gemm_hmma_x1(
    const __half* __restrict__ Ahi, const __half* __restrict__ Bhi,
    float* __restrict__ C,
    __half* __restrict__ Qh, __half* __restrict__ Kh, __half* __restrict__ Vh,
    const float* __restrict__ cs, const float* __restrict__ sn,
    int N, int K)
{
    extern __shared__ char smem[];
    const uint32_t sb = smem_u32(smem);
    const int tid = threadIdx.x;
    const int wid = tid >> 5, lane = tid & 31;
    const int wm = wid & 1;
    const int wn = wid >> 1;
    const int lr = lane >> 2;
    const int m0 = blockIdx.y * BM, n0 = blockIdx.x * BN;

    float acc[4][4][4];
#pragma unroll
    for (int mt = 0; mt < 4; mt++)
#pragma unroll
        for (int nt = 0; nt < 4; nt++)
#pragma unroll
            for (int r = 0; r < 4; r++) acc[mt][nt][r] = 0.f;

    const int NIT = K / BK;   // 64

    load_stage(sb,            Ahi, Bhi, m0, n0, 0,  K, tid);
    CP_COMMIT();
    load_stage(sb + STAGE_SM, Ahi, Bhi, m0, n0, BK, K, tid);
    CP_COMMIT();

    const int a_row = lane & 15;
    const int a_chi = lane >> 4;
    const int b_row = (lane & 7) + ((lane >> 4) << 3);
    const int b_chi = (lane >> 3) & 1;

    for (int it = 0; it < NIT; ++it) {
        CP_WAIT1();
        __syncthreads();
        if (it + 2 < NIT)
            load_stage(sb + ((it + 2) % 3) * STAGE_SM,
                       Ahi, Bhi, m0, n0, (it + 2) * BK, K, tid);
        CP_COMMIT();   // always commit to keep group counting fixed

        const uint32_t sA = sb + (it % 3) * STAGE_SM;
        const uint32_t sB = sA + TILE_SM;
#pragma unroll
        for (int kk = 0; kk < 4; kk++) {     // four k16 slices in BK=64
            uint32_t ah[4][4], bh[2][4];
#pragma unroll
            for (int mt = 0; mt < 4; mt++) {
                const int r = wm * 64 + mt * 16 + a_row;
                const int c = kk * 2 + a_chi;
                ldsm_x4(ah[mt], sA + r * 128 + (SWZ8(r, c) << 4));
            }
#pragma unroll
            for (int ntp = 0; ntp < 2; ntp++) {
                const int r = wn * 32 + ntp * 16 + b_row;
                const int c = kk * 2 + b_chi;
                ldsm_x4(bh[ntp], sB + r * 128 + (SWZ8(r, c) << 4));
            }
#pragma unroll
            for (int mt = 0; mt < 4; mt++)
#pragma unroll
                for (int nt = 0; nt < 4; nt++)
                    mma_f16(acc[mt][nt], ah[mt], bh[nt >> 1] + (nt & 1) * 2);
        }
    }

    if (!EPI) {
#pragma unroll
        for (int mt = 0; mt < 4; mt++) {
            const int row = m0 + wm * 64 + mt * 16 + lr;
#pragma unroll
            for (int nt = 0; nt < 4; nt++) {
                const int col = n0 + wn * 32 + nt * 8 + (lane & 3) * 2;
                float2* p0 = (float2*)&C[(size_t)row * N + col];
                float2* p1 = (float2*)&C[(size_t)(row + 8) * N + col];
                *p0 = make_float2(acc[mt][nt][0], acc[mt][nt][1]);
                *p1 = make_float2(acc[mt][nt][2], acc[mt][nt][3]);
            }
        }
    } else {
        // regions: [0,NQ): Q + rope; [NQ,NQ+NKV): K + rope; rest: V
        __half* Dh;
        int dstride, coff;
        bool dorope;
        if (n0 < NQ)            { Dh = Qh; dstride = NQ;  coff = 0;        dorope = true; }
        else if (n0 < NQ + NKV) { Dh = Kh; dstride = NKV; coff = NQ;       dorope = true; }
        else                    { Dh = Vh; dstride = NKV; coff = NQ + NKV; dorope = false; }
#pragma unroll
        for (int mt = 0; mt < 4; mt++) {
#pragma unroll
            for (int nt = 0; nt < 4; nt++) {
                const int col = n0 + wn * 32 + nt * 8 + (lane & 3) * 2;
                const int fi = (col & 127) >> 1;
#pragma unroll
                for (int r = 0; r < 2; r++) {
                    const int row = m0 + wm * 64 + mt * 16 + lr + 8 * r;
                    float x0 = acc[mt][nt][2 * r];
                    float x1 = acc[mt][nt][2 * r + 1];
                    float y0 = x0, y1 = x1;
                    if (dorope) {
                        const int s = row & (Sv - 1);
                        const float c  = __ldg(cs + s * 64 + fi);
                        const float sv = __ldg(sn + s * 64 + fi);
                        y0 = x0 * c - x1 * sv;
                        y1 = x0 * sv + x1 * c;
                    }
                    *(uint32_t*)&Dh[(size_t)row * dstride + (col - coff)] =
                        pack2h(y0, y1);
                }
            }
        }
    }
}

// ---------------------------------------------------------------------------
// HMMA flash attention, fp16 1-pass (unchanged from R14, proven).
// CTA = 64 q-rows, 128 threads, K/V tiles of 32 rows double-buffered,
// Q register-resident. 51KB smem, 3 CTAs/SM, longest-first order.
// ---------------------------------------------------------------------------
#define FROWB 272
#define FQ_SM    (64 * FROWB)
#define FK_HALF  (32 * FROWB)
#define SM_KV    FQ_SM
#define KV_STAGE (2 * FK_HALF)
#define FLASH_SMEM (SM_KV + 2 * KV_STAGE)   // 52224

__device__ __forceinline__ void flash_load_kv(
    uint32_t sb, int stage,
    const __half* __restrict__ Kh, const __half* __restrict__ Vh,
    size_t gbase, int tid)
{
#pragma unroll
    for (int j = 0; j < 8; j++) {
        const int t = j >> 2;
        const int cc = tid + (j & 3) * 128;
        const int row = cc >> 4, c16 = cc & 15;
        const __half* g = (t == 0) ? Kh : Vh;
        const uint32_t soff = sb + SM_KV + stage * KV_STAGE + t * FK_HALF
                              + row * FROWB + c16 * 16;
        cp16(soff, g + gbase + (size_t)row * NKV + c16 * 8);
    }
}

__global__ __launch_bounds__(128, 3) void flash_hmma(
    const __half* __restrict__ Qh_g,
    const __half* __restrict__ Kh_g, const __half* __restrict__ Vh_g,
    __half* __restrict__ Oh)
{
    extern __shared__ char smem[];
    const uint32_t sb = smem_u32(smem);
    const int tid = threadIdx.x, w = tid >> 5, lane = tid & 31;
    const int lr = lane >> 2, lc = lane & 3;
    const int qb = gridDim.x - 1 - blockIdx.x;   // longest-first
    const int q0 = qb * 64, h = blockIdx.y, b = blockIdx.z;
    const int kvh = h >> 2;
    const float scale = 0.08838834764831845f;

    {
        const size_t gq = ((size_t)(b * Sv + q0)) * NQ + h * HDv;
#pragma unroll
        for (int j = 0; j < 8; j++) {
            const int cc = tid + j * 128;
            const int row = cc >> 4, c16 = cc & 15;
            cp16(sb + row * FROWB + c16 * 16,
                 Qh_g + gq + (size_t)row * NQ + c16 * 8);
        }
    }
    CP_COMMIT();
    flash_load_kv(sb, 0, Kh_g, Vh_g, ((size_t)(b * Sv)) * NKV + kvh * HDv, tid);
    CP_COMMIT();

    const int a_row = lane & 15;
    const int a_cb  = (lane >> 4) << 4;
    const int b_row = (lane & 7) + ((lane >> 4) << 3);
    const int b_cb  = ((lane >> 3) & 1) << 4;

    CP_WAIT1();
    __syncthreads();
    uint32_t qh[8][4];
#pragma unroll
    for (int kf = 0; kf < 8; kf++)
        ldsm_x4(qh[kf], sb + (w * 16 + a_row) * FROWB + kf * 32 + a_cb);

    float o[16][4];
#pragma unroll
    for (int i = 0; i < 16; i++)
#pragma unroll
        for (int j = 0; j < 4; j++) o[i][j] = 0.f;
    float mrow[2] = {-1e30f, -1e30f};
    float lrow[2] = {0.f, 0.f};

    const int ktmax = 2 * qb + 1;
    for (int kt = 0; kt <= ktmax; ++kt) {
        CP_WAIT0();
        __syncthreads();
        if (kt < ktmax) {
            flash_load_kv(sb, (kt + 1) & 1, Kh_g, Vh_g,
                          ((size_t)(b * Sv + (kt + 1) * 32)) * NKV + kvh * HDv, tid);
            CP_COMMIT();
        }

        const int k0 = kt * 32;
        if (k0 > q0 + w * 16 + 15) continue;

        const uint32_t Kst = sb + SM_KV + (kt & 1) * KV_STAGE;
        const uint32_t Vst = Kst + FK_HALF;

        float s[4][4];
#pragma unroll
        for (int nf = 0; nf < 4; nf++)
#pragma unroll
            for (int r = 0; r < 4; r++) s[nf][r] = 0.f;

#pragma unroll
        for (int kf = 0; kf < 8; kf++) {
#pragma unroll
            for (int nfp = 0; nfp < 2; nfp++) {
                const uint32_t kaddr = Kst + (nfp * 16 + b_row) * FROWB + kf * 32 + b_cb;
                uint32_t bh4[4];
                ldsm_x4(bh4, kaddr);
                mma_f16(s[2 * nfp],     qh[kf], bh4);
                mma_f16(s[2 * nfp + 1], qh[kf], bh4 + 2);
            }
        }

        const bool diag = (k0 + 31 > q0 + w * 16);
#pragma unroll
        for (int r = 0; r < 2; r++) {
            const int qrow = q0 + w * 16 + lr + 8 * r;
            float mx = -1e30f;
#pragma unroll
            for (int nf = 0; nf < 4; nf++) {
                float v0 = s[nf][2 * r] * scale;
                float v1 = s[nf][2 * r + 1] * scale;
                if (diag) {
                    const int col = k0 + nf * 8 + lc * 2;
                    if (col > qrow) v0 = -1e30f;
                    if (col + 1 > qrow) v1 = -1e30f;
                }
                s[nf][2 * r] = v0;
                s[nf][2 * r + 1] = v1;
                mx = fmaxf(mx, fmaxf(v0, v1));
            }
            mx = fmaxf(mx, __shfl_xor_sync(0xffffffffu, mx, 1));
            mx = fmaxf(mx, __shfl_xor_sync(0xffffffffu, mx, 2));
            const float m_new = fmaxf(mrow[r], mx);
            const float alpha = __expf(mrow[r] - m_new);
            mrow[r] = m_new;
            float sum = 0.f;
#pragma unroll
            for (int nf = 0; nf < 4; nf++) {
                float p0 = __expf(s[nf][2 * r] - m_new);
                float p1 = __expf(s[nf][2 * r + 1] - m_new);
                s[nf][2 * r] = p0;
                s[nf][2 * r + 1] = p1;
                sum += p0 + p1;
            }
            sum += __shfl_xor_sync(0xffffffffu, sum, 1);
            sum += __shfl_xor_sync(0xffffffffu, sum, 2);
            lrow[r] = lrow[r] * alpha + sum;
#pragma unroll
            for (int nf2 = 0; nf2 < 16; nf2++) {
                o[nf2][2 * r] *= alpha;
                o[nf2][2 * r + 1] *= alpha;
            }
        }

        uint32_t phi[2][4];
#pragma unroll
        for (int kf2 = 0; kf2 < 2; kf2++) {
#pragma unroll
            for (int m = 0; m < 2; m++) {
                const int nf = 2 * kf2 + m;
                phi[kf2][2 * m]     = pack2h(s[nf][0], s[nf][1]);
                phi[kf2][2 * m + 1] = pack2h(s[nf][2], s[nf][3]);
            }
        }

#pragma unroll
        for (int kf2 = 0; kf2 < 2; kf2++) {
#pragma unroll
            for (int nfp = 0; nfp < 8; nfp++) {
                const uint32_t va = Vst + (kf2 * 16 + (lane & 15)) * FROWB
                                    + (nfp * 16 + ((lane >> 4) << 3)) * 2;
                uint32_t bh4[4];
                ldsm_x4_t(bh4, va);
                mma_f16(o[2 * nfp],     phi[kf2], bh4);
                mma_f16(o[2 * nfp + 1], phi[kf2], bh4 + 2);
            }
        }
    }

#pragma unroll
    for (int r = 0; r < 2; r++) {
        const float inv = 1.f / lrow[r];
        const int row = q0 + w * 16 + lr + 8 * r;
        const size_t base = ((size_t)(b * Sv + row)) * NQ + h * HDv + lc * 2;
#pragma unroll
        for (int nf2 = 0; nf2 < 16; nf2++) {
            *(uint32_t*)&Oh[base + nf2 * 8] =
                pack2h(o[nf2][2 * r] * inv, o[nf2][2 * r + 1] * inv);
        }
    }
}

// ---------------------------------------------------------------------------
// Launch. Inputs: 0=x 1=cos 2=sin 3=positions 4=mask 5=wq 6=wk 7=wv 8=wo
// ---------------------------------------------------------------------------
extern "C" void kernel_launch(void* const* d_in, const int* in_sizes, int n_in,
                              void* d_out, int out_size)
{
    const float* x  = (const float*)d_in[0];
    const float* fc = (const float*)d_in[1];
    const float* fs = (const float*)d_in[2];
    const float* wq = (const float*)d_in[5];
    const float* wk = (const float*)d_in[6];
    const float* wv = (const float*)d_in[7];
    const float* wo = (const float*)d_in[8];
    float* out = (float*)d_out;

    __half *xh, *wh, *oh, *ah, *qrh, *krh, *vsh;
    cudaGetSymbolAddress((void**)&xh, g_x_hi);
    cudaGetSymbolAddress((void**)&wh, g_wqkv_hi);
    cudaGetSymbolAddress((void**)&oh, g_wo_hi);
    cudaGetSymbolAddress((void**)&ah, g_at_hi);
    cudaGetSymbolAddress((void**)&qrh, g_qr_hi);
    cudaGetSymbolAddress((void**)&krh, g_kr_hi);
    cudaGetSymbolAddress((void**)&vsh, g_vs_hi);

    // conversions: everything -> fp16 (concatenated wqkv), 4x ILP
    {
        long n4;
        n4 = (long)Mv * Dv / 4;
        cvt_hi<<<cvt_grid(n4), 256>>>(x, xh, n4);
        n4 = (long)NQ * Dv / 4;
        cvt_hi<<<cvt_grid(n4), 256>>>(wq, wh, n4);
        n4 = (long)NKV * Dv / 4;
        cvt_hi<<<cvt_grid(n4), 256>>>(wk, wh + (size_t)NQ * Dv, n4);
        cvt_hi<<<cvt_grid(n4), 256>>>(wv, wh + (size_t)(NQ + NKV) * Dv, n4);
        n4 = (long)Dv * NQ / 4;
        cvt_hi<<<cvt_grid(n4), 256>>>(wo, oh, n4);
    }

    cudaFuncSetAttribute(gemm_hmma_x1<true>,
                         cudaFuncAttributeMaxDynamicSharedMemorySize, GEMM_SMEM);
    cudaFuncSetAttribute(gemm_hmma_x1<false>,
                         cudaFuncAttributeMaxDynamicSharedMemorySize, GEMM_SMEM);

    // Fused QKV projection + RoPE (1-pass, BK=64)
    gemm_hmma_x1<true><<<dim3(NQKV / BN, Mv / BM), 256, GEMM_SMEM>>>(
        xh, wh, nullptr,
        qrh, krh, vsh, fc, fs, NQKV, Dv);

    // Flash attention (fp16 1-pass, 3 CTAs/SM, longest-first)
    cudaFuncSetAttribute(flash_hmma, cudaFuncAttributeMaxDynamicSharedMemorySize, FLASH_SMEM);
    flash_hmma<<<dim3(Sv / 64, Hv, Bv), 128, FLASH_SMEM>>>(
        qrh, krh, vsh, ah);

    // Output projection (1-pass, BK=64)
    gemm_hmma_x1<false><<<dim3(NQ / BN, Mv / BM), 256, GEMM_SMEM>>>(
        ah, oh, out,
        nullptr, nullptr, nullptr, nullptr, nullptr, NQ, Dv);
}